// round 5
// baseline (speedup 1.0000x reference)
#include <cuda_runtime.h>
#include <cstdint>
#include <cstddef>

#define DEPN  96
#define HEADN 96
#define BSZN  16
#define DIMN  512
#define RELN  128

// Scratch for projection outputs (fp32): P[(d*16+b)][e], Q[(h*16+b)][e]
__device__ float g_P[DEPN * BSZN * DIMN];
__device__ float g_Q[HEADN * BSZN * DIMN];

__device__ __forceinline__ uint32_t f2tf32(float x) {
    uint32_t r;
    asm("cvt.rna.tf32.f32 %0, %1;" : "=r"(r) : "f"(x));
    return r;
}

__device__ __forceinline__ void mma_tf32(float* c, const uint32_t* a, const uint32_t* b) {
    asm volatile(
        "mma.sync.aligned.m16n8k8.row.col.f32.tf32.tf32.f32 "
        "{%0,%1,%2,%3}, {%4,%5,%6,%7}, {%8,%9}, {%0,%1,%2,%3};\n"
        : "+f"(c[0]), "+f"(c[1]), "+f"(c[2]), "+f"(c[3])
        : "r"(a[0]), "r"(a[1]), "r"(a[2]), "r"(a[3]), "r"(b[0]), "r"(b[1]));
}

// ---------------------------------------------------------------------------
// Kernel 1: projections.  C[m, e] = sum_i In[m, i] * Wt[e, woff + i]
// Tile 128(m) x 128(e), K-chunk 32, 256 threads = 8 warps (2m x 4n),
// warp tile 64x32 via tf32 m16n8k8.
// ---------------------------------------------------------------------------
__global__ __launch_bounds__(256, 2)
void proj_kernel(const float* __restrict__ outs,
                 const float* __restrict__ gs,
                 const float* __restrict__ Wt)
{
    const int which = blockIdx.z;
    const float* __restrict__ In = which ? gs : outs;
    float* __restrict__ Out = which ? g_Q : g_P;
    const int woff = which ? DIMN : 0;
    const int m0 = blockIdx.y * 128;
    const int e0 = blockIdx.x * 128;

    __shared__ __align__(16) float As[128 * 36];
    __shared__ __align__(16) float Bs[128 * 36];

    const int tid = threadIdx.x;
    const int wid = tid >> 5;
    const int lane = tid & 31;
    const int wm = wid >> 2;   // 0..1
    const int wn = wid & 3;    // 0..3
    const int g = lane >> 2;   // 0..7
    const int tg = lane & 3;   // 0..3

    float c[4][4][4];
    #pragma unroll
    for (int i = 0; i < 4; i++)
        #pragma unroll
        for (int j = 0; j < 4; j++)
            #pragma unroll
            for (int k = 0; k < 4; k++) c[i][j][k] = 0.f;

    const float4* In4 = reinterpret_cast<const float4*>(In);
    const float4* Wt4 = reinterpret_cast<const float4*>(Wt);

    for (int k0 = 0; k0 < DIMN; k0 += 32) {
        __syncthreads();
        // A tile: 128 x 32 fp32, direct vector copy + tf32 round
        #pragma unroll
        for (int i = 0; i < 4; i++) {
            int idx = i * 256 + tid;
            int m = idx >> 3, kk4 = idx & 7;
            float4 v = In4[(size_t)(m0 + m) * (DIMN / 4) + (k0 >> 2) + kk4];
            uint4 u;
            u.x = f2tf32(v.x); u.y = f2tf32(v.y); u.z = f2tf32(v.z); u.w = f2tf32(v.w);
            *reinterpret_cast<uint4*>(&As[m * 36 + kk4 * 4]) = u;
        }
        // B tile: Bs[n][kk] = Wt[e0+n][woff+k0+kk]  (n-major, stride 36)
        #pragma unroll
        for (int i = 0; i < 4; i++) {
            int idx = i * 256 + tid;
            int n = idx >> 3, kk4 = idx & 7;
            float4 v = Wt4[(size_t)(e0 + n) * (2 * DIMN / 4) + ((woff + k0) >> 2) + kk4];
            uint4 u;
            u.x = f2tf32(v.x); u.y = f2tf32(v.y); u.z = f2tf32(v.z); u.w = f2tf32(v.w);
            *reinterpret_cast<uint4*>(&Bs[n * 36 + kk4 * 4]) = u;
        }
        __syncthreads();
        #pragma unroll
        for (int ks = 0; ks < 4; ks++) {
            const int kb = ks * 8 + tg;
            uint32_t a[4][4];
            #pragma unroll
            for (int mf = 0; mf < 4; mf++) {
                int r = wm * 64 + mf * 16 + g;
                a[mf][0] = __float_as_uint(As[r * 36 + kb]);
                a[mf][1] = __float_as_uint(As[(r + 8) * 36 + kb]);
                a[mf][2] = __float_as_uint(As[r * 36 + kb + 4]);
                a[mf][3] = __float_as_uint(As[(r + 8) * 36 + kb + 4]);
            }
            #pragma unroll
            for (int nf = 0; nf < 4; nf++) {
                int n = wn * 32 + nf * 8 + g;
                uint32_t bb[2];
                bb[0] = __float_as_uint(Bs[n * 36 + kb]);
                bb[1] = __float_as_uint(Bs[n * 36 + kb + 4]);
                #pragma unroll
                for (int mf = 0; mf < 4; mf++)
                    mma_tf32(c[mf][nf], a[mf], bb);
            }
        }
    }

    // Epilogue: write fp32 C to scratch
    #pragma unroll
    for (int mf = 0; mf < 4; mf++) {
        #pragma unroll
        for (int nf = 0; nf < 4; nf++) {
            int r = m0 + wm * 64 + mf * 16 + g;
            int col = e0 + wn * 32 + nf * 8 + 2 * tg;
            *reinterpret_cast<float2*>(&Out[(size_t)r * DIMN + col]) =
                make_float2(c[mf][nf][0], c[mf][nf][1]);
            *reinterpret_cast<float2*>(&Out[(size_t)(r + 8) * DIMN + col]) =
                make_float2(c[mf][nf][2], c[mf][nf][3]);
        }
    }
}

// ---------------------------------------------------------------------------
// Kernel 2: fused pairwise scores + log-softmax.
// Block = (b, dblk, hblk): 128 rows (16 dep x 8 head) x 128 rel, K = 512.
// Row m in tile: di = m>>3, hi = m&7.
// A[m,k] = relu(P[d,b,k] + Q[h,b,k] + bt[k]),  B[k,n] = Wp[n,k].
// Then per row r over 129 = [0, scores+bp]: log_softmax, write out.
// ---------------------------------------------------------------------------
__global__ __launch_bounds__(256, 2)
void rel_kernel(const float* __restrict__ Wp,
                const float* __restrict__ bt,
                const float* __restrict__ bp,
                float* __restrict__ out)
{
    const int hblk = blockIdx.x;  // 0..11
    const int dblk = blockIdx.y;  // 0..5
    const int b = blockIdx.z;     // 0..15

    __shared__ __align__(16) union SM {
        struct {
            float As[128 * 36];
            float Bs[128 * 36];
            float Ps[16 * 32];
            float Qs[8 * 32];
            float bts[32];
        } s;
        float Ssm[64 * 132];
    } sm;
    __shared__ float bps[RELN];

    const int tid = threadIdx.x;
    const int wid = tid >> 5;
    const int lane = tid & 31;
    const int wm = wid >> 2;   // 0..1
    const int wn = wid & 3;    // 0..3
    const int g = lane >> 2;
    const int tg = lane & 3;

    if (tid < RELN) bps[tid] = bp[tid];

    float c[4][4][4];
    #pragma unroll
    for (int i = 0; i < 4; i++)
        #pragma unroll
        for (int j = 0; j < 4; j++)
            #pragma unroll
            for (int k = 0; k < 4; k++) c[i][j][k] = 0.f;

    const float4* P4 = reinterpret_cast<const float4*>(g_P);
    const float4* Q4 = reinterpret_cast<const float4*>(g_Q);
    const float4* Wp4 = reinterpret_cast<const float4*>(Wp);
    const float4* bt4 = reinterpret_cast<const float4*>(bt);

    for (int k0 = 0; k0 < DIMN; k0 += 32) {
        __syncthreads();
        // Stage P rows (16x32), Q rows (8x32), bt chunk (32)
        if (tid < 128) {
            int r = tid >> 3, kk4 = tid & 7;
            *reinterpret_cast<float4*>(&sm.s.Ps[r * 32 + kk4 * 4]) =
                P4[(size_t)((dblk * 16 + r) * BSZN + b) * (DIMN / 4) + (k0 >> 2) + kk4];
        } else if (tid < 192) {
            int t = tid - 128;
            int r = t >> 3, kk4 = t & 7;
            *reinterpret_cast<float4*>(&sm.s.Qs[r * 32 + kk4 * 4]) =
                Q4[(size_t)((hblk * 8 + r) * BSZN + b) * (DIMN / 4) + (k0 >> 2) + kk4];
        } else if (tid < 200) {
            int kk4 = tid - 192;
            *reinterpret_cast<float4*>(&sm.s.bts[kk4 * 4]) = bt4[(k0 >> 2) + kk4];
        }
        // Stage B tile: Bs[n][kk] = Wp[n][k0+kk]
        #pragma unroll
        for (int i = 0; i < 4; i++) {
            int idx = i * 256 + tid;
            int n = idx >> 3, kk4 = idx & 7;
            float4 v = Wp4[(size_t)n * (DIMN / 4) + (k0 >> 2) + kk4];
            uint4 u;
            u.x = f2tf32(v.x); u.y = f2tf32(v.y); u.z = f2tf32(v.z); u.w = f2tf32(v.w);
            *reinterpret_cast<uint4*>(&sm.s.Bs[n * 36 + kk4 * 4]) = u;
        }
        __syncthreads();
        // Build A tile: relu(P + Q + bt), tf32-rounded. 128x32, 16 elems/thread.
        #pragma unroll
        for (int i = 0; i < 16; i++) {
            int idx = i * 256 + tid;
            int m = idx >> 5, k = idx & 31;
            float v = sm.s.Ps[(m >> 3) * 32 + k] + sm.s.Qs[(m & 7) * 32 + k] + sm.s.bts[k];
            sm.s.As[m * 36 + k] = __uint_as_float(f2tf32(fmaxf(v, 0.f)));
        }
        __syncthreads();
        #pragma unroll
        for (int ks = 0; ks < 4; ks++) {
            const int kb = ks * 8 + tg;
            uint32_t a[4][4];
            #pragma unroll
            for (int mf = 0; mf < 4; mf++) {
                int r = wm * 64 + mf * 16 + g;
                a[mf][0] = __float_as_uint(sm.s.As[r * 36 + kb]);
                a[mf][1] = __float_as_uint(sm.s.As[(r + 8) * 36 + kb]);
                a[mf][2] = __float_as_uint(sm.s.As[r * 36 + kb + 4]);
                a[mf][3] = __float_as_uint(sm.s.As[(r + 8) * 36 + kb + 4]);
            }
            #pragma unroll
            for (int nf = 0; nf < 4; nf++) {
                int n = wn * 32 + nf * 8 + g;
                uint32_t bb[2];
                bb[0] = __float_as_uint(sm.s.Bs[n * 36 + kb]);
                bb[1] = __float_as_uint(sm.s.Bs[n * 36 + kb + 4]);
                #pragma unroll
                for (int mf = 0; mf < 4; mf++)
                    mma_tf32(c[mf][nf], a[mf], bb);
            }
        }
    }

    // Epilogue: two half-tiles of 64 rows through the Ssm staging buffer
    // (aliases As/Bs — safe after the sync below).
    #pragma unroll 1
    for (int half = 0; half < 2; half++) {
        __syncthreads();
        if (wm == half) {
            #pragma unroll
            for (int mf = 0; mf < 4; mf++) {
                #pragma unroll
                for (int nf = 0; nf < 4; nf++) {
                    int rl = mf * 16 + g;
                    int col = wn * 32 + nf * 8 + 2 * tg;
                    *reinterpret_cast<float2*>(&sm.Ssm[rl * 132 + col]) =
                        make_float2(c[mf][nf][0], c[mf][nf][1]);
                    *reinterpret_cast<float2*>(&sm.Ssm[(rl + 8) * 132 + col]) =
                        make_float2(c[mf][nf][2], c[mf][nf][3]);
                }
            }
        }
        __syncthreads();
        // 8 warps x 8 rows: per row, 32 lanes x 4 scores, +bp, concat nil(0),
        // log-softmax over 129, write 129 contiguous fp32.
        #pragma unroll
        for (int i = 0; i < 8; i++) {
            int rl = wid * 8 + i;
            float4 v = *reinterpret_cast<const float4*>(&sm.Ssm[rl * 132 + lane * 4]);
            v.x += bps[lane * 4 + 0];
            v.y += bps[lane * 4 + 1];
            v.z += bps[lane * 4 + 2];
            v.w += bps[lane * 4 + 3];
            float mx = fmaxf(fmaxf(v.x, v.y), fmaxf(v.z, v.w));
            #pragma unroll
            for (int off = 16; off > 0; off >>= 1)
                mx = fmaxf(mx, __shfl_xor_sync(0xffffffffu, mx, off));
            mx = fmaxf(mx, 0.f);  // nil column
            float se = __expf(v.x - mx) + __expf(v.y - mx) +
                       __expf(v.z - mx) + __expf(v.w - mx);
            #pragma unroll
            for (int off = 16; off > 0; off >>= 1)
                se += __shfl_xor_sync(0xffffffffu, se, off);
            se += __expf(-mx);  // nil column contribution
            float lse = mx + __logf(se);
            int row = half * 64 + rl;
            int d = dblk * 16 + (row >> 3);
            int h = hblk * 8 + (row & 7);
            float* op = out + (size_t)((d * BSZN + b) * HEADN + h) * (RELN + 1);
            if (lane == 0) op[0] = -lse;
            op[1 + lane * 4 + 0] = v.x - lse;
            op[1 + lane * 4 + 1] = v.y - lse;
            op[1 + lane * 4 + 2] = v.z - lse;
            op[1 + lane * 4 + 3] = v.w - lse;
        }
    }
}

// ---------------------------------------------------------------------------
extern "C" void kernel_launch(void* const* d_in, const int* in_sizes, int n_in,
                              void* d_out, int out_size) {
    const float* outs = (const float*)d_in[0];  // [96,16,512]
    const float* gs   = (const float*)d_in[1];  // [96,16,512]
    const float* Wt   = (const float*)d_in[2];  // [512,1024]
    const float* bt   = (const float*)d_in[3];  // [512]
    const float* Wp   = (const float*)d_in[4];  // [128,512]
    const float* bp   = (const float*)d_in[5];  // [128]
    float* out = (float*)d_out;                 // [96,16,96,129]

    (void)in_sizes; (void)n_in; (void)out_size;

    dim3 pg(DIMN / 128, (DEPN * BSZN) / 128, 2);  // (4, 12, 2)
    proj_kernel<<<pg, 256>>>(outs, gs, Wt);

    dim3 mg(HEADN / 8, DEPN / 16, BSZN);          // (12, 6, 16)
    rel_kernel<<<mg, 256>>>(Wp, bt, bp, out);
}

// round 7
// speedup vs baseline: 1.6426x; 1.6426x over previous
#include <cuda_runtime.h>
#include <cuda_bf16.h>
#include <cstdint>
#include <cstddef>

#define DEPN  96
#define HEADN 96
#define BSZN  16
#define DIMN  512
#define RELN  128

// Scratch for projection outputs (fp32): P[(d*16+b)][e], Q[(h*16+b)][e]
__device__ float g_P[DEPN * BSZN * DIMN];
__device__ float g_Q[HEADN * BSZN * DIMN];

__device__ __forceinline__ uint32_t f2tf32(float x) {
    uint32_t r;
    asm("cvt.rna.tf32.f32 %0, %1;" : "=r"(r) : "f"(x));
    return r;
}

// pack two floats -> bf16x2 (lo = first arg)
__device__ __forceinline__ uint32_t f2bf2(float lo, float hi) {
    uint32_t r;
    asm("cvt.rn.bf16x2.f32 %0, %1, %2;" : "=r"(r) : "f"(hi), "f"(lo));
    return r;
}

__device__ __forceinline__ uint32_t smem_u32(const void* p) {
    uint32_t a;
    asm("{ .reg .u64 t; cvta.to.shared.u64 t, %1; cvt.u32.u64 %0, t; }"
        : "=r"(a) : "l"(p));
    return a;
}

__device__ __forceinline__ void ldsm_x4(uint32_t* r, uint32_t addr) {
    asm volatile("ldmatrix.sync.aligned.m8n8.x4.shared.b16 {%0,%1,%2,%3}, [%4];"
        : "=r"(r[0]), "=r"(r[1]), "=r"(r[2]), "=r"(r[3]) : "r"(addr));
}

__device__ __forceinline__ void mma_bf16(float* c, const uint32_t* a, const uint32_t* b) {
    asm volatile(
        "mma.sync.aligned.m16n8k16.row.col.f32.bf16.bf16.f32 "
        "{%0,%1,%2,%3}, {%4,%5,%6,%7}, {%8,%9}, {%0,%1,%2,%3};\n"
        : "+f"(c[0]), "+f"(c[1]), "+f"(c[2]), "+f"(c[3])
        : "r"(a[0]), "r"(a[1]), "r"(a[2]), "r"(a[3]), "r"(b[0]), "r"(b[1]));
}

__device__ __forceinline__ void mma_tf32(float* c, const uint32_t* a, const uint32_t* b) {
    asm volatile(
        "mma.sync.aligned.m16n8k8.row.col.f32.tf32.tf32.f32 "
        "{%0,%1,%2,%3}, {%4,%5,%6,%7}, {%8,%9}, {%0,%1,%2,%3};\n"
        : "+f"(c[0]), "+f"(c[1]), "+f"(c[2]), "+f"(c[3])
        : "r"(a[0]), "r"(a[1]), "r"(a[2]), "r"(a[3]), "r"(b[0]), "r"(b[1]));
}

// ---------------------------------------------------------------------------
// Kernel 1: projections (tf32, unchanged from round 4 — known good, 19us).
// ---------------------------------------------------------------------------
__global__ __launch_bounds__(256, 2)
void proj_kernel(const float* __restrict__ outs,
                 const float* __restrict__ gs,
                 const float* __restrict__ Wt)
{
    const int which = blockIdx.z;
    const float* __restrict__ In = which ? gs : outs;
    float* __restrict__ Out = which ? g_Q : g_P;
    const int woff = which ? DIMN : 0;
    const int m0 = blockIdx.y * 128;
    const int e0 = blockIdx.x * 128;

    __shared__ __align__(16) float As[128 * 36];
    __shared__ __align__(16) float Bs[128 * 36];

    const int tid = threadIdx.x;
    const int wid = tid >> 5;
    const int lane = tid & 31;
    const int wm = wid >> 2;
    const int wn = wid & 3;
    const int g = lane >> 2;
    const int tg = lane & 3;

    float c[4][4][4];
    #pragma unroll
    for (int i = 0; i < 4; i++)
        #pragma unroll
        for (int j = 0; j < 4; j++)
            #pragma unroll
            for (int k = 0; k < 4; k++) c[i][j][k] = 0.f;

    const float4* In4 = reinterpret_cast<const float4*>(In);
    const float4* Wt4 = reinterpret_cast<const float4*>(Wt);

    for (int k0 = 0; k0 < DIMN; k0 += 32) {
        __syncthreads();
        #pragma unroll
        for (int i = 0; i < 4; i++) {
            int idx = i * 256 + tid;
            int m = idx >> 3, kk4 = idx & 7;
            float4 v = In4[(size_t)(m0 + m) * (DIMN / 4) + (k0 >> 2) + kk4];
            uint4 u;
            u.x = f2tf32(v.x); u.y = f2tf32(v.y); u.z = f2tf32(v.z); u.w = f2tf32(v.w);
            *reinterpret_cast<uint4*>(&As[m * 36 + kk4 * 4]) = u;
        }
        #pragma unroll
        for (int i = 0; i < 4; i++) {
            int idx = i * 256 + tid;
            int n = idx >> 3, kk4 = idx & 7;
            float4 v = Wt4[(size_t)(e0 + n) * (2 * DIMN / 4) + ((woff + k0) >> 2) + kk4];
            uint4 u;
            u.x = f2tf32(v.x); u.y = f2tf32(v.y); u.z = f2tf32(v.z); u.w = f2tf32(v.w);
            *reinterpret_cast<uint4*>(&Bs[n * 36 + kk4 * 4]) = u;
        }
        __syncthreads();
        #pragma unroll
        for (int ks = 0; ks < 4; ks++) {
            const int kb = ks * 8 + tg;
            uint32_t a[4][4];
            #pragma unroll
            for (int mf = 0; mf < 4; mf++) {
                int r = wm * 64 + mf * 16 + g;
                a[mf][0] = __float_as_uint(As[r * 36 + kb]);
                a[mf][1] = __float_as_uint(As[(r + 8) * 36 + kb]);
                a[mf][2] = __float_as_uint(As[r * 36 + kb + 4]);
                a[mf][3] = __float_as_uint(As[(r + 8) * 36 + kb + 4]);
            }
            #pragma unroll
            for (int nf = 0; nf < 4; nf++) {
                int n = wn * 32 + nf * 8 + g;
                uint32_t bb[2];
                bb[0] = __float_as_uint(Bs[n * 36 + kb]);
                bb[1] = __float_as_uint(Bs[n * 36 + kb + 4]);
                #pragma unroll
                for (int mf = 0; mf < 4; mf++)
                    mma_tf32(c[mf][nf], a[mf], bb);
            }
        }
    }

    #pragma unroll
    for (int mf = 0; mf < 4; mf++) {
        #pragma unroll
        for (int nf = 0; nf < 4; nf++) {
            int r = m0 + wm * 64 + mf * 16 + g;
            int col = e0 + wn * 32 + nf * 8 + 2 * tg;
            *reinterpret_cast<float2*>(&Out[(size_t)r * DIMN + col]) =
                make_float2(c[mf][nf][0], c[mf][nf][1]);
            *reinterpret_cast<float2*>(&Out[(size_t)(r + 8) * DIMN + col]) =
                make_float2(c[mf][nf][2], c[mf][nf][3]);
        }
    }
}

// ---------------------------------------------------------------------------
// Kernel 2: fused pairwise scores + log-softmax.
// bf16 mma.m16n8k16 + ldmatrix.x4. Block = 128 rows (16 dep x 8 head) x 128
// rel, K = 512 in 8 chunks of 64. SMEM rows padded to 144B (9x16B) so every
// ldmatrix phase (8 lanes) hits 8 distinct bank groups: granule = 9*row mod 8.
// A[m,k] = bf16(relu(P[d,b,k]+Q[h,b,k]+bt[k])), B[n,k] = bf16(Wp[n,k]).
// ---------------------------------------------------------------------------
#define ASTRIDE 144            // bytes per smem row (64 bf16 + 8 pad)
#define BS_OFF  (128 * ASTRIDE)  // 18432

__global__ __launch_bounds__(256, 2)
void rel_kernel(const float* __restrict__ Wp,
                const float* __restrict__ bt,
                const float* __restrict__ bp,
                float* __restrict__ out)
{
    __shared__ __align__(16) char smraw[2 * 128 * ASTRIDE];  // 36864B; epilogue reuses as float[64*132]
    __shared__ float bps[RELN];

    const int hblk = blockIdx.x;  // 0..11
    const int dblk = blockIdx.y;  // 0..5
    const int b = blockIdx.z;     // 0..15

    const int tid = threadIdx.x;
    const int wid = tid >> 5;
    const int lane = tid & 31;
    const int wm = wid >> 2;   // 0..1
    const int wn = wid & 3;    // 0..3
    const int g = lane >> 2;
    const int tg = lane & 3;

    if (tid < RELN) bps[tid] = bp[tid];

    float c[4][4][4];
    #pragma unroll
    for (int i = 0; i < 4; i++)
        #pragma unroll
        for (int j = 0; j < 4; j++)
            #pragma unroll
            for (int k = 0; k < 4; k++) c[i][j][k] = 0.f;

    const float4* P4 = reinterpret_cast<const float4*>(g_P);
    const float4* Q4 = reinterpret_cast<const float4*>(g_Q);
    const float4* Wp4 = reinterpret_cast<const float4*>(Wp);
    const float4* bt4 = reinterpret_cast<const float4*>(bt);

    const uint32_t AsB = smem_u32(smraw);
    const uint32_t BsB = AsB + BS_OFF;

    // Build mapping: tg16 = tid>>4 selects row-within-pass, cc = tid&15 selects
    // the float4 column. m = pass*16 + tg16 -> m&7 = tg16&7 (thread-constant!),
    // m>>3 = pass*2 + (tg16>>3).
    const int tg16 = tid >> 4;
    const int cc = tid & 15;
    const size_t qrow = (size_t)(hblk * 8 + (tg16 & 7)) * BSZN + b;

    // ldmatrix per-lane addresses (thread-constant parts)
    const uint32_t aRowOff = (uint32_t)(lane & 15) * ASTRIDE + (uint32_t)(lane >> 4) * 16;
    const uint32_t bRow = (uint32_t)(wn * 32 + ((lane >> 4) << 3) + (lane & 7));
    const uint32_t bOff = bRow * ASTRIDE + (uint32_t)((lane >> 3) & 1) * 16;

    #pragma unroll 1
    for (int j = 0; j < 8; j++) {
        const int kq = j * 16;  // float4 index of chunk start
        __syncthreads();

        // --- Build A tile: bf16(relu(P + Q + bt)) ---
        float4 q4 = Q4[qrow * (DIMN / 4) + kq + cc];
        float4 t4 = bt4[kq + cc];
        const float qx = q4.x + t4.x, qy = q4.y + t4.y;
        const float qz = q4.z + t4.z, qw = q4.w + t4.w;
        #pragma unroll
        for (int pass = 0; pass < 8; pass++) {
            int m = pass * 16 + tg16;
            int pr = dblk * 16 + pass * 2 + (tg16 >> 3);
            float4 p4 = P4[((size_t)pr * BSZN + b) * (DIMN / 4) + kq + cc];
            uint2 u;
            u.x = f2bf2(fmaxf(p4.x + qx, 0.f), fmaxf(p4.y + qy, 0.f));
            u.y = f2bf2(fmaxf(p4.z + qz, 0.f), fmaxf(p4.w + qw, 0.f));
            *reinterpret_cast<uint2*>(smraw + m * ASTRIDE + cc * 8) = u;
        }
        // --- Build B tile: bf16(Wp) ---
        #pragma unroll
        for (int pass = 0; pass < 8; pass++) {
            int n = pass * 16 + tg16;
            float4 w4 = Wp4[(size_t)n * (DIMN / 4) + kq + cc];
            uint2 u;
            u.x = f2bf2(w4.x, w4.y);
            u.y = f2bf2(w4.z, w4.w);
            *reinterpret_cast<uint2*>(smraw + BS_OFF + n * ASTRIDE + cc * 8) = u;
        }
        __syncthreads();

        // --- MMA: 4 k16-steps over the 64-wide chunk ---
        #pragma unroll
        for (int ks = 0; ks < 4; ks++) {
            uint32_t a[4][4];
            #pragma unroll
            for (int mf = 0; mf < 4; mf++)
                ldsm_x4(a[mf], AsB + (uint32_t)(wm * 64 + mf * 16) * ASTRIDE
                                     + aRowOff + ks * 32);
            uint32_t bb[8];
            ldsm_x4(&bb[0], BsB + bOff + ks * 32);
            ldsm_x4(&bb[4], BsB + 16 * ASTRIDE + bOff + ks * 32);
            #pragma unroll
            for (int nf = 0; nf < 4; nf++)
                #pragma unroll
                for (int mf = 0; mf < 4; mf++)
                    mma_bf16(c[mf][nf], a[mf], &bb[nf * 2]);
        }
    }

    // --- Epilogue: two half-tiles of 64 rows through float staging buffer ---
    float* Ssm = reinterpret_cast<float*>(smraw);  // 64*132 floats = 33792B
    #pragma unroll 1
    for (int half = 0; half < 2; half++) {
        __syncthreads();
        if (wm == half) {
            #pragma unroll
            for (int mf = 0; mf < 4; mf++) {
                #pragma unroll
                for (int nf = 0; nf < 4; nf++) {
                    int rl = mf * 16 + g;
                    int col = wn * 32 + nf * 8 + 2 * tg;
                    *reinterpret_cast<float2*>(&Ssm[rl * 132 + col]) =
                        make_float2(c[mf][nf][0], c[mf][nf][1]);
                    *reinterpret_cast<float2*>(&Ssm[(rl + 8) * 132 + col]) =
                        make_float2(c[mf][nf][2], c[mf][nf][3]);
                }
            }
        }
        __syncthreads();
        #pragma unroll
        for (int i = 0; i < 8; i++) {
            int rl = wid * 8 + i;
            float4 v = *reinterpret_cast<const float4*>(&Ssm[rl * 132 + lane * 4]);
            v.x += bps[lane * 4 + 0];
            v.y += bps[lane * 4 + 1];
            v.z += bps[lane * 4 + 2];
            v.w += bps[lane * 4 + 3];
            float mx = fmaxf(fmaxf(v.x, v.y), fmaxf(v.z, v.w));
            #pragma unroll
            for (int off = 16; off > 0; off >>= 1)
                mx = fmaxf(mx, __shfl_xor_sync(0xffffffffu, mx, off));
            mx = fmaxf(mx, 0.f);  // nil column
            float se = __expf(v.x - mx) + __expf(v.y - mx) +
                       __expf(v.z - mx) + __expf(v.w - mx);
            #pragma unroll
            for (int off = 16; off > 0; off >>= 1)
                se += __shfl_xor_sync(0xffffffffu, se, off);
            se += __expf(-mx);  // nil column contribution
            float lse = mx + __logf(se);
            int row = half * 64 + rl;
            int d = dblk * 16 + (row >> 3);
            int h = hblk * 8 + (row & 7);
            float* op = out + (size_t)((d * BSZN + b) * HEADN + h) * (RELN + 1);
            if (lane == 0) op[0] = -lse;
            op[1 + lane * 4 + 0] = v.x - lse;
            op[1 + lane * 4 + 1] = v.y - lse;
            op[1 + lane * 4 + 2] = v.z - lse;
            op[1 + lane * 4 + 3] = v.w - lse;
        }
    }
}

// ---------------------------------------------------------------------------
extern "C" void kernel_launch(void* const* d_in, const int* in_sizes, int n_in,
                              void* d_out, int out_size) {
    const float* outs = (const float*)d_in[0];  // [96,16,512]
    const float* gs   = (const float*)d_in[1];  // [96,16,512]
    const float* Wt   = (const float*)d_in[2];  // [512,1024]
    const float* bt   = (const float*)d_in[3];  // [512]
    const float* Wp   = (const float*)d_in[4];  // [128,512]
    const float* bp   = (const float*)d_in[5];  // [128]
    float* out = (float*)d_out;                 // [96,16,96,129]

    (void)in_sizes; (void)n_in; (void)out_size;

    dim3 pg(DIMN / 128, (DEPN * BSZN) / 128, 2);  // (4, 12, 2)
    proj_kernel<<<pg, 256>>>(outs, gs, Wt);

    dim3 mg(HEADN / 8, DEPN / 16, BSZN);          // (12, 6, 16)
    rel_kernel<<<mg, 256>>>(Wp, bt, bp, out);
}

// round 8
// speedup vs baseline: 1.7299x; 1.0531x over previous
#include <cuda_runtime.h>
#include <cuda_bf16.h>
#include <cstdint>
#include <cstddef>

#define DEPN  96
#define HEADN 96
#define BSZN  16
#define DIMN  512
#define RELN  128

// Scratch: P' = outs@Wt1 + bt (fp32), Q = gs@Wt2 (fp32), Wp in bf16.
__device__ float g_P[DEPN * BSZN * DIMN];
__device__ float g_Q[HEADN * BSZN * DIMN];
__device__ __align__(16) uint8_t g_Wpb[RELN * DIMN * 2];

__device__ __forceinline__ uint32_t f2tf32(float x) {
    uint32_t r;
    asm("cvt.rna.tf32.f32 %0, %1;" : "=r"(r) : "f"(x));
    return r;
}

// pack two floats -> bf16x2 (lo = first arg)
__device__ __forceinline__ uint32_t f2bf2(float lo, float hi) {
    uint32_t r;
    asm("cvt.rn.bf16x2.f32 %0, %1, %2;" : "=r"(r) : "f"(hi), "f"(lo));
    return r;
}

__device__ __forceinline__ uint32_t smem_u32(const void* p) {
    uint32_t a;
    asm("{ .reg .u64 t; cvta.to.shared.u64 t, %1; cvt.u32.u64 %0, t; }"
        : "=r"(a) : "l"(p));
    return a;
}

__device__ __forceinline__ void cp16(uint32_t dst, const void* src) {
    asm volatile("cp.async.cg.shared.global [%0], [%1], 16;"
        :: "r"(dst), "l"(src));
}
#define CP_COMMIT() asm volatile("cp.async.commit_group;" ::: "memory")
#define CP_WAIT0()  asm volatile("cp.async.wait_group 0;" ::: "memory")

__device__ __forceinline__ void ldsm_x4(uint32_t* r, uint32_t addr) {
    asm volatile("ldmatrix.sync.aligned.m8n8.x4.shared.b16 {%0,%1,%2,%3}, [%4];"
        : "=r"(r[0]), "=r"(r[1]), "=r"(r[2]), "=r"(r[3]) : "r"(addr));
}

__device__ __forceinline__ void mma_bf16(float* c, const uint32_t* a, const uint32_t* b) {
    asm volatile(
        "mma.sync.aligned.m16n8k16.row.col.f32.bf16.bf16.f32 "
        "{%0,%1,%2,%3}, {%4,%5,%6,%7}, {%8,%9}, {%0,%1,%2,%3};\n"
        : "+f"(c[0]), "+f"(c[1]), "+f"(c[2]), "+f"(c[3])
        : "r"(a[0]), "r"(a[1]), "r"(a[2]), "r"(a[3]), "r"(b[0]), "r"(b[1]));
}

__device__ __forceinline__ void mma_tf32(float* c, const uint32_t* a, const uint32_t* b) {
    asm volatile(
        "mma.sync.aligned.m16n8k8.row.col.f32.tf32.tf32.f32 "
        "{%0,%1,%2,%3}, {%4,%5,%6,%7}, {%8,%9}, {%0,%1,%2,%3};\n"
        : "+f"(c[0]), "+f"(c[1]), "+f"(c[2]), "+f"(c[3])
        : "r"(a[0]), "r"(a[1]), "r"(a[2]), "r"(a[3]), "r"(b[0]), "r"(b[1]));
}

// ---------------------------------------------------------------------------
// Kernel 0: Wp -> bf16 (128 x 512), once.
// ---------------------------------------------------------------------------
__global__ void wpb_kernel(const float* __restrict__ Wp)
{
    int idx = blockIdx.x * 256 + threadIdx.x;           // 0 .. 16383 float4s
    float4 w = reinterpret_cast<const float4*>(Wp)[idx];
    uint2 u;
    u.x = f2bf2(w.x, w.y);
    u.y = f2bf2(w.z, w.w);
    *reinterpret_cast<uint2*>(g_Wpb + (size_t)idx * 8) = u;
}

// ---------------------------------------------------------------------------
// Kernel 1: projections (tf32). For which==0 (g_P) the bt bias is folded in.
// ---------------------------------------------------------------------------
__global__ __launch_bounds__(256, 2)
void proj_kernel(const float* __restrict__ outs,
                 const float* __restrict__ gs,
                 const float* __restrict__ Wt,
                 const float* __restrict__ bt)
{
    const int which = blockIdx.z;
    const float* __restrict__ In = which ? gs : outs;
    float* __restrict__ Out = which ? g_Q : g_P;
    const int woff = which ? DIMN : 0;
    const int m0 = blockIdx.y * 128;
    const int e0 = blockIdx.x * 128;

    __shared__ __align__(16) float As[128 * 36];
    __shared__ __align__(16) float Bs[128 * 36];

    const int tid = threadIdx.x;
    const int wid = tid >> 5;
    const int lane = tid & 31;
    const int wm = wid >> 2;
    const int wn = wid & 3;
    const int g = lane >> 2;
    const int tg = lane & 3;

    float c[4][4][4];
    #pragma unroll
    for (int i = 0; i < 4; i++)
        #pragma unroll
        for (int j = 0; j < 4; j++)
            #pragma unroll
            for (int k = 0; k < 4; k++) c[i][j][k] = 0.f;

    const float4* In4 = reinterpret_cast<const float4*>(In);
    const float4* Wt4 = reinterpret_cast<const float4*>(Wt);

    for (int k0 = 0; k0 < DIMN; k0 += 32) {
        __syncthreads();
        #pragma unroll
        for (int i = 0; i < 4; i++) {
            int idx = i * 256 + tid;
            int m = idx >> 3, kk4 = idx & 7;
            float4 v = In4[(size_t)(m0 + m) * (DIMN / 4) + (k0 >> 2) + kk4];
            uint4 u;
            u.x = f2tf32(v.x); u.y = f2tf32(v.y); u.z = f2tf32(v.z); u.w = f2tf32(v.w);
            *reinterpret_cast<uint4*>(&As[m * 36 + kk4 * 4]) = u;
        }
        #pragma unroll
        for (int i = 0; i < 4; i++) {
            int idx = i * 256 + tid;
            int n = idx >> 3, kk4 = idx & 7;
            float4 v = Wt4[(size_t)(e0 + n) * (2 * DIMN / 4) + ((woff + k0) >> 2) + kk4];
            uint4 u;
            u.x = f2tf32(v.x); u.y = f2tf32(v.y); u.z = f2tf32(v.z); u.w = f2tf32(v.w);
            *reinterpret_cast<uint4*>(&Bs[n * 36 + kk4 * 4]) = u;
        }
        __syncthreads();
        #pragma unroll
        for (int ks = 0; ks < 4; ks++) {
            const int kb = ks * 8 + tg;
            uint32_t a[4][4];
            #pragma unroll
            for (int mf = 0; mf < 4; mf++) {
                int r = wm * 64 + mf * 16 + g;
                a[mf][0] = __float_as_uint(As[r * 36 + kb]);
                a[mf][1] = __float_as_uint(As[(r + 8) * 36 + kb]);
                a[mf][2] = __float_as_uint(As[r * 36 + kb + 4]);
                a[mf][3] = __float_as_uint(As[(r + 8) * 36 + kb + 4]);
            }
            #pragma unroll
            for (int nf = 0; nf < 4; nf++) {
                int n = wn * 32 + nf * 8 + g;
                uint32_t bb[2];
                bb[0] = __float_as_uint(Bs[n * 36 + kb]);
                bb[1] = __float_as_uint(Bs[n * 36 + kb + 4]);
                #pragma unroll
                for (int mf = 0; mf < 4; mf++)
                    mma_tf32(c[mf][nf], a[mf], bb);
            }
        }
    }

    #pragma unroll
    for (int mf = 0; mf < 4; mf++) {
        #pragma unroll
        for (int nf = 0; nf < 4; nf++) {
            int r = m0 + wm * 64 + mf * 16 + g;
            int col = e0 + wn * 32 + nf * 8 + 2 * tg;
            float b0 = 0.f, b1 = 0.f;
            if (!which) { b0 = bt[col]; b1 = bt[col + 1]; }
            *reinterpret_cast<float2*>(&Out[(size_t)r * DIMN + col]) =
                make_float2(c[mf][nf][0] + b0, c[mf][nf][1] + b1);
            *reinterpret_cast<float2*>(&Out[(size_t)(r + 8) * DIMN + col]) =
                make_float2(c[mf][nf][2] + b0, c[mf][nf][3] + b1);
        }
    }
}

// ---------------------------------------------------------------------------
// Kernel 2: fused pairwise scores + log-softmax, cp.async pipelined.
// Block = 128 rows (16 dep x 8 head) x 128 rel, K = 512 in 8 chunks of 64.
// Per chunk: cp.async stages raw P rows (16x64 f32), Q rows (8x64 f32) and the
// bf16 B tile (128x64, 144B rows) double-buffered; A = bf16(relu(P'+Q)) built
// from SMEM; MMA via ldmatrix.x4 + mma.m16n8k16.
// ---------------------------------------------------------------------------
#define ASTRIDE 144
// dynamic smem layout
#define OFF_BPS   0                         // 512B
#define STAGE_SZ  24576                     // Ps 4096 + Qs 2048 + Bs 18432
#define OFF_ST(s) (1024 + (s) * STAGE_SZ)
#define ST_PS     0
#define ST_QS     4096
#define ST_BS     6144
#define OFF_AB(p) (1024 + 2 * STAGE_SZ + (p) * (128 * ASTRIDE))
#define REL_SMEM  (1024 + 2 * STAGE_SZ + 2 * 128 * ASTRIDE)   // 87040

__global__ __launch_bounds__(256, 2)
void rel_kernel(const float* __restrict__ bp,
                float* __restrict__ out)
{
    extern __shared__ __align__(16) char dsm[];
    const uint32_t smb = smem_u32(dsm);
    float* bps = reinterpret_cast<float*>(dsm + OFF_BPS);

    const int hblk = blockIdx.x;  // 0..11
    const int dblk = blockIdx.y;  // 0..5
    const int b = blockIdx.z;     // 0..15

    const int tid = threadIdx.x;
    const int wid = tid >> 5;
    const int lane = tid & 31;
    const int wm = wid >> 2;   // 0..1
    const int wn = wid & 3;    // 0..3
    const int g = lane >> 2;
    const int tg = lane & 3;

    if (tid < RELN) bps[tid] = bp[tid];

    float c[4][4][4];
    #pragma unroll
    for (int i = 0; i < 4; i++)
        #pragma unroll
        for (int j = 0; j < 4; j++)
            #pragma unroll
            for (int k = 0; k < 4; k++) c[i][j][k] = 0.f;

    // thread-constant pieces
    const int tg16 = tid >> 4;       // 0..15
    const int cc = tid & 15;         // 0..15
    const int hi = tg16 & 7;
    const int prb = tg16 >> 3;       // 0/1

    // cp.async source base addresses (bytes into global rows)
    const uint8_t* gP = reinterpret_cast<const uint8_t*>(g_P)
        + ((size_t)(dblk * 16 + tg16) * BSZN + b) * (DIMN * 4);
    const uint8_t* gQ = reinterpret_cast<const uint8_t*>(g_Q)
        + ((size_t)(hblk * 8 + (tid >> 4)) * BSZN + b) * (DIMN * 4);

    // ldmatrix per-lane address pieces
    const uint32_t aRowOff = (uint32_t)(lane & 15) * ASTRIDE + (uint32_t)(lane >> 4) * 16;
    const uint32_t bRow = (uint32_t)(wn * 32 + ((lane >> 4) << 3) + (lane & 7));
    const uint32_t bOff = bRow * ASTRIDE + (uint32_t)((lane >> 3) & 1) * 16;

    // ---- stage issuer: copy chunk j into stage s ----
    auto issue_stage = [&](int j, int s) {
        const uint32_t stb = smb + OFF_ST(s);
        // Ps: 16 rows x 64 f32 -> 256 x 16B, 1 per thread
        cp16(stb + ST_PS + (uint32_t)tg16 * 256 + (uint32_t)cc * 16,
             gP + (size_t)j * 256 + (size_t)cc * 16);
        // Qs: 8 rows x 64 f32 -> 128 x 16B, threads 0..127
        if (tid < 128)
            cp16(stb + ST_QS + (uint32_t)(tid >> 4) * 256 + (uint32_t)cc * 16,
                 gQ + (size_t)j * 256 + (size_t)cc * 16);
        // Bs: 128 rows x 64 bf16 (128B data per 144B row) -> 1024 x 16B, 4/thread
        #pragma unroll
        for (int i = 0; i < 4; i++) {
            int o = i * 256 + tid;
            int n = o >> 3, ch = o & 7;
            cp16(stb + ST_BS + (uint32_t)n * ASTRIDE + (uint32_t)ch * 16,
                 g_Wpb + (size_t)n * (DIMN * 2) + (size_t)j * 128 + (size_t)ch * 16);
        }
        CP_COMMIT();
    };

    // ---- A-tile builder: bf16(relu(P' + Q)) for chunk staged in s -> Ab[p] ----
    auto build_A = [&](int s, int p) {
        const char* stc = dsm + OFF_ST(s);
        char* ab = dsm + OFF_AB(p);
        float4 q = *reinterpret_cast<const float4*>(stc + ST_QS + hi * 256 + cc * 16);
        #pragma unroll
        for (int pass = 0; pass < 8; pass++) {
            int pr = pass * 2 + prb;
            float4 pv = *reinterpret_cast<const float4*>(stc + ST_PS + pr * 256 + cc * 16);
            uint2 u;
            u.x = f2bf2(fmaxf(pv.x + q.x, 0.f), fmaxf(pv.y + q.y, 0.f));
            u.y = f2bf2(fmaxf(pv.z + q.z, 0.f), fmaxf(pv.w + q.w, 0.f));
            *reinterpret_cast<uint2*>(ab + (pass * 16 + tg16) * ASTRIDE + cc * 8) = u;
        }
    };

    // ---- prologue ----
    issue_stage(0, 0);
    CP_WAIT0();
    __syncthreads();
    build_A(0, 0);

    // ---- pipelined mainloop ----
    #pragma unroll 1
    for (int j = 0; j < 8; j++) {
        const int cur = j & 1;
        __syncthreads();                      // A(j) visible; prev MMA done
        if (j < 7) issue_stage(j + 1, cur ^ 1);

        const uint32_t AsB = smb + OFF_AB(cur);
        const uint32_t BsB = smb + OFF_ST(cur) + ST_BS;
        #pragma unroll
        for (int ks = 0; ks < 4; ks++) {
            uint32_t a[4][4];
            #pragma unroll
            for (int mf = 0; mf < 4; mf++)
                ldsm_x4(a[mf], AsB + (uint32_t)(wm * 64 + mf * 16) * ASTRIDE
                                     + aRowOff + ks * 32);
            uint32_t bb[8];
            ldsm_x4(&bb[0], BsB + bOff + ks * 32);
            ldsm_x4(&bb[4], BsB + 16 * ASTRIDE + bOff + ks * 32);
            #pragma unroll
            for (int nf = 0; nf < 4; nf++)
                #pragma unroll
                for (int mf = 0; mf < 4; mf++)
                    mma_bf16(c[mf][nf], a[mf], &bb[nf * 2]);
        }

        if (j < 7) {
            CP_WAIT0();
            __syncthreads();                  // staged data visible to all
            build_A(cur ^ 1, cur ^ 1);
        }
    }

    // ---- epilogue: two half-tiles of 64 rows via float staging buffer ----
    float* Ssm = reinterpret_cast<float*>(dsm + 1024);   // 64*132 f = 33792B
    #pragma unroll 1
    for (int half = 0; half < 2; half++) {
        __syncthreads();
        if (wm == half) {
            #pragma unroll
            for (int mf = 0; mf < 4; mf++) {
                #pragma unroll
                for (int nf = 0; nf < 4; nf++) {
                    int rl = mf * 16 + g;
                    int col = wn * 32 + nf * 8 + 2 * tg;
                    *reinterpret_cast<float2*>(&Ssm[rl * 132 + col]) =
                        make_float2(c[mf][nf][0], c[mf][nf][1]);
                    *reinterpret_cast<float2*>(&Ssm[(rl + 8) * 132 + col]) =
                        make_float2(c[mf][nf][2], c[mf][nf][3]);
                }
            }
        }
        __syncthreads();
        #pragma unroll
        for (int i = 0; i < 8; i++) {
            int rl = wid * 8 + i;
            float4 v = *reinterpret_cast<const float4*>(&Ssm[rl * 132 + lane * 4]);
            v.x += bps[lane * 4 + 0];
            v.y += bps[lane * 4 + 1];
            v.z += bps[lane * 4 + 2];
            v.w += bps[lane * 4 + 3];
            float mx = fmaxf(fmaxf(v.x, v.y), fmaxf(v.z, v.w));
            #pragma unroll
            for (int off = 16; off > 0; off >>= 1)
                mx = fmaxf(mx, __shfl_xor_sync(0xffffffffu, mx, off));
            mx = fmaxf(mx, 0.f);  // nil column
            float se = __expf(v.x - mx) + __expf(v.y - mx) +
                       __expf(v.z - mx) + __expf(v.w - mx);
            #pragma unroll
            for (int off = 16; off > 0; off >>= 1)
                se += __shfl_xor_sync(0xffffffffu, se, off);
            se += __expf(-mx);  // nil column contribution
            float lse = mx + __logf(se);
            int row = half * 64 + rl;
            int d = dblk * 16 + (row >> 3);
            int h = hblk * 8 + (row & 7);
            float* op = out + (size_t)((d * BSZN + b) * HEADN + h) * (RELN + 1);
            if (lane == 0) op[0] = -lse;
            op[1 + lane * 4 + 0] = v.x - lse;
            op[1 + lane * 4 + 1] = v.y - lse;
            op[1 + lane * 4 + 2] = v.z - lse;
            op[1 + lane * 4 + 3] = v.w - lse;
        }
    }
}

// ---------------------------------------------------------------------------
extern "C" void kernel_launch(void* const* d_in, const int* in_sizes, int n_in,
                              void* d_out, int out_size) {
    const float* outs = (const float*)d_in[0];  // [96,16,512]
    const float* gs   = (const float*)d_in[1];  // [96,16,512]
    const float* Wt   = (const float*)d_in[2];  // [512,1024]
    const float* bt   = (const float*)d_in[3];  // [512]
    const float* Wp   = (const float*)d_in[4];  // [128,512]
    const float* bp   = (const float*)d_in[5];  // [128]
    float* out = (float*)d_out;                 // [96,16,96,129]

    (void)in_sizes; (void)n_in; (void)out_size;

    static bool attr_set = false;
    if (!attr_set) {
        cudaFuncSetAttribute(rel_kernel,
                             cudaFuncAttributeMaxDynamicSharedMemorySize,
                             REL_SMEM);
        attr_set = true;
    }

    wpb_kernel<<<RELN * DIMN / 4 / 256, 256>>>(Wp);      // 64 blocks

    dim3 pg(DIMN / 128, (DEPN * BSZN) / 128, 2);  // (4, 12, 2)
    proj_kernel<<<pg, 256>>>(outs, gs, Wt, bt);

    dim3 mg(HEADN / 8, DEPN / 16, BSZN);          // (12, 6, 16)
    rel_kernel<<<mg, 256, REL_SMEM>>>(bp, out);
}

// round 10
// speedup vs baseline: 1.7984x; 1.0396x over previous
#include <cuda_runtime.h>
#include <cuda_bf16.h>
#include <cstdint>
#include <cstddef>

#define DEPN  96
#define HEADN 96
#define BSZN  16
#define DIMN  512
#define RELN  128

// Scratch: P' = bf16(outs@Wt1 + bt), Q = bf16(gs@Wt2), Wp in bf16.
__device__ __align__(16) uint8_t g_Pb[DEPN * BSZN * DIMN * 2];
__device__ __align__(16) uint8_t g_Qb[HEADN * BSZN * DIMN * 2];
__device__ __align__(16) uint8_t g_Wpb[RELN * DIMN * 2];

__device__ __forceinline__ uint32_t f2tf32(float x) {
    uint32_t r;
    asm("cvt.rna.tf32.f32 %0, %1;" : "=r"(r) : "f"(x));
    return r;
}

// pack two floats -> bf16x2 (lo = first arg)
__device__ __forceinline__ uint32_t f2bf2(float lo, float hi) {
    uint32_t r;
    asm("cvt.rn.bf16x2.f32 %0, %1, %2;" : "=r"(r) : "f"(hi), "f"(lo));
    return r;
}

// relu(p + q) on bf16x2 pairs
__device__ __forceinline__ uint32_t bf2_addrelu(uint32_t p, uint32_t q) {
    uint32_t s, r;
    asm("add.rn.bf16x2 %0, %1, %2;" : "=r"(s) : "r"(p), "r"(q));
    asm("max.bf16x2 %0, %1, %2;" : "=r"(r) : "r"(s), "r"(0u));
    return r;
}

__device__ __forceinline__ uint32_t smem_u32(const void* p) {
    uint32_t a;
    asm("{ .reg .u64 t; cvta.to.shared.u64 t, %1; cvt.u32.u64 %0, t; }"
        : "=r"(a) : "l"(p));
    return a;
}

__device__ __forceinline__ void cp16(uint32_t dst, const void* src) {
    asm volatile("cp.async.cg.shared.global [%0], [%1], 16;"
        :: "r"(dst), "l"(src));
}
#define CP_COMMIT() asm volatile("cp.async.commit_group;" ::: "memory")
#define CP_WAIT0()  asm volatile("cp.async.wait_group 0;" ::: "memory")

__device__ __forceinline__ void ldsm_x4(uint32_t* r, uint32_t addr) {
    asm volatile("ldmatrix.sync.aligned.m8n8.x4.shared.b16 {%0,%1,%2,%3}, [%4];"
        : "=r"(r[0]), "=r"(r[1]), "=r"(r[2]), "=r"(r[3]) : "r"(addr));
}

__device__ __forceinline__ void mma_bf16(float* c, const uint32_t* a, const uint32_t* b) {
    asm volatile(
        "mma.sync.aligned.m16n8k16.row.col.f32.bf16.bf16.f32 "
        "{%0,%1,%2,%3}, {%4,%5,%6,%7}, {%8,%9}, {%0,%1,%2,%3};\n"
        : "+f"(c[0]), "+f"(c[1]), "+f"(c[2]), "+f"(c[3])
        : "r"(a[0]), "r"(a[1]), "r"(a[2]), "r"(a[3]), "r"(b[0]), "r"(b[1]));
}

__device__ __forceinline__ void mma_tf32(float* c, const uint32_t* a, const uint32_t* b) {
    asm volatile(
        "mma.sync.aligned.m16n8k8.row.col.f32.tf32.tf32.f32 "
        "{%0,%1,%2,%3}, {%4,%5,%6,%7}, {%8,%9}, {%0,%1,%2,%3};\n"
        : "+f"(c[0]), "+f"(c[1]), "+f"(c[2]), "+f"(c[3])
        : "r"(a[0]), "r"(a[1]), "r"(a[2]), "r"(a[3]), "r"(b[0]), "r"(b[1]));
}

// ---------------------------------------------------------------------------
// Kernel 0: Wp -> bf16 (128 x 512), once.
// ---------------------------------------------------------------------------
__global__ void wpb_kernel(const float* __restrict__ Wp)
{
    int idx = blockIdx.x * 256 + threadIdx.x;           // 0 .. 16383 float4s
    float4 w = reinterpret_cast<const float4*>(Wp)[idx];
    uint2 u;
    u.x = f2bf2(w.x, w.y);
    u.y = f2bf2(w.z, w.w);
    *reinterpret_cast<uint2*>(g_Wpb + (size_t)idx * 8) = u;
}

// ---------------------------------------------------------------------------
// Kernel 1: projections (tf32 mma), outputs bf16; bt folded into P.
// ---------------------------------------------------------------------------
__global__ __launch_bounds__(256, 2)
void proj_kernel(const float* __restrict__ outs,
                 const float* __restrict__ gs,
                 const float* __restrict__ Wt,
                 const float* __restrict__ bt)
{
    const int which = blockIdx.z;
    const float* __restrict__ In = which ? gs : outs;
    uint8_t* __restrict__ Outb = which ? g_Qb : g_Pb;
    const int woff = which ? DIMN : 0;
    const int m0 = blockIdx.y * 128;
    const int e0 = blockIdx.x * 128;

    __shared__ __align__(16) float As[128 * 36];
    __shared__ __align__(16) float Bs[128 * 36];

    const int tid = threadIdx.x;
    const int wid = tid >> 5;
    const int lane = tid & 31;
    const int wm = wid >> 2;
    const int wn = wid & 3;
    const int g = lane >> 2;
    const int tg = lane & 3;

    float c[4][4][4];
    #pragma unroll
    for (int i = 0; i < 4; i++)
        #pragma unroll
        for (int j = 0; j < 4; j++)
            #pragma unroll
            for (int k = 0; k < 4; k++) c[i][j][k] = 0.f;

    const float4* In4 = reinterpret_cast<const float4*>(In);
    const float4* Wt4 = reinterpret_cast<const float4*>(Wt);

    for (int k0 = 0; k0 < DIMN; k0 += 32) {
        __syncthreads();
        #pragma unroll
        for (int i = 0; i < 4; i++) {
            int idx = i * 256 + tid;
            int m = idx >> 3, kk4 = idx & 7;
            float4 v = In4[(size_t)(m0 + m) * (DIMN / 4) + (k0 >> 2) + kk4];
            uint4 u;
            u.x = f2tf32(v.x); u.y = f2tf32(v.y); u.z = f2tf32(v.z); u.w = f2tf32(v.w);
            *reinterpret_cast<uint4*>(&As[m * 36 + kk4 * 4]) = u;
        }
        #pragma unroll
        for (int i = 0; i < 4; i++) {
            int idx = i * 256 + tid;
            int n = idx >> 3, kk4 = idx & 7;
            float4 v = Wt4[(size_t)(e0 + n) * (2 * DIMN / 4) + ((woff + k0) >> 2) + kk4];
            uint4 u;
            u.x = f2tf32(v.x); u.y = f2tf32(v.y); u.z = f2tf32(v.z); u.w = f2tf32(v.w);
            *reinterpret_cast<uint4*>(&Bs[n * 36 + kk4 * 4]) = u;
        }
        __syncthreads();
        #pragma unroll
        for (int ks = 0; ks < 4; ks++) {
            const int kb = ks * 8 + tg;
            uint32_t a[4][4];
            #pragma unroll
            for (int mf = 0; mf < 4; mf++) {
                int r = wm * 64 + mf * 16 + g;
                a[mf][0] = __float_as_uint(As[r * 36 + kb]);
                a[mf][1] = __float_as_uint(As[(r + 8) * 36 + kb]);
                a[mf][2] = __float_as_uint(As[r * 36 + kb + 4]);
                a[mf][3] = __float_as_uint(As[(r + 8) * 36 + kb + 4]);
            }
            #pragma unroll
            for (int nf = 0; nf < 4; nf++) {
                int n = wn * 32 + nf * 8 + g;
                uint32_t bb[2];
                bb[0] = __float_as_uint(Bs[n * 36 + kb]);
                bb[1] = __float_as_uint(Bs[n * 36 + kb + 4]);
                #pragma unroll
                for (int mf = 0; mf < 4; mf++)
                    mma_tf32(c[mf][nf], a[mf], bb);
            }
        }
    }

    #pragma unroll
    for (int mf = 0; mf < 4; mf++) {
        #pragma unroll
        for (int nf = 0; nf < 4; nf++) {
            int r = m0 + wm * 64 + mf * 16 + g;
            int col = e0 + wn * 32 + nf * 8 + 2 * tg;
            float b0 = 0.f, b1 = 0.f;
            if (!which) { b0 = bt[col]; b1 = bt[col + 1]; }
            uint32_t u01 = f2bf2(c[mf][nf][0] + b0, c[mf][nf][1] + b1);
            uint32_t u23 = f2bf2(c[mf][nf][2] + b0, c[mf][nf][3] + b1);
            *reinterpret_cast<uint32_t*>(Outb + ((size_t)r * DIMN + col) * 2) = u01;
            *reinterpret_cast<uint32_t*>(Outb + ((size_t)(r + 8) * DIMN + col) * 2) = u23;
        }
    }
}

// ---------------------------------------------------------------------------
// Kernel 2: fused pairwise scores + log-softmax.
// P/Q tiles (bf16) staged ONCE in smem; B double-buffered via cp.async;
// A = relu(Pb+Qb) in bf16x2 math, double-buffered; one __syncthreads/chunk.
// Block = 128 rows (16 dep x 8 head) x 128 rel, K = 512 in 8 chunks of 64.
// ---------------------------------------------------------------------------
#define ASTRIDE 144
#define OFF_BPS 0
#define OFF_PB  1024                        // 16 KB (16 rows x 1024 B)
#define OFF_QB  (OFF_PB + 16384)            // 8 KB
#define OFF_B(s) (25600 + (s) * (128 * ASTRIDE))
#define OFF_A(p) (25600 + 2 * 128 * ASTRIDE + (p) * (128 * ASTRIDE))
#define REL_SMEM (25600 + 4 * 128 * ASTRIDE)   // 99328 B

__global__ __launch_bounds__(256, 2)
void rel_kernel(const float* __restrict__ bp,
                float* __restrict__ out)
{
    extern __shared__ __align__(16) char dsm[];
    const uint32_t smb = smem_u32(dsm);
    float* bps = reinterpret_cast<float*>(dsm + OFF_BPS);

    const int hblk = blockIdx.x;  // 0..11
    const int dblk = blockIdx.y;  // 0..5
    const int b = blockIdx.z;     // 0..15

    const int tid = threadIdx.x;
    const int wid = tid >> 5;
    const int lane = tid & 31;
    const int wm = wid >> 2;   // 0..1
    const int wn = wid & 3;    // 0..3
    const int g = lane >> 2;
    const int tg = lane & 3;

    if (tid < RELN) bps[tid] = bp[tid];

    float c[4][4][4];
    #pragma unroll
    for (int i = 0; i < 4; i++)
        #pragma unroll
        for (int j = 0; j < 4; j++)
            #pragma unroll
            for (int k = 0; k < 4; k++) c[i][j][k] = 0.f;

    // thread-constant pieces
    const int tg16 = tid >> 4;       // 0..15
    const int cc = tid & 15;         // 0..15
    const int hi = tg16 & 7;
    const int prb = tg16 >> 3;       // 0/1

    // ldmatrix per-lane address pieces
    const uint32_t aRowOff = (uint32_t)(lane & 15) * ASTRIDE + (uint32_t)(lane >> 4) * 16;
    const uint32_t bRow = (uint32_t)(wn * 32 + ((lane >> 4) << 3) + (lane & 7));
    const uint32_t bOff = bRow * ASTRIDE + (uint32_t)((lane >> 3) & 1) * 16;

    // ---- B-stage issuer: copy bf16 Wp chunk j into stage s ----
    auto issue_B = [&](int j, int s) {
        const uint32_t stb = smb + OFF_B(s);
        #pragma unroll
        for (int i = 0; i < 4; i++) {
            int o = i * 256 + tid;
            int n = o >> 3, ch = o & 7;
            cp16(stb + (uint32_t)n * ASTRIDE + (uint32_t)ch * 16,
                 g_Wpb + (size_t)n * (DIMN * 2) + (size_t)j * 128 + (size_t)ch * 16);
        }
        CP_COMMIT();
    };

    // ---- A builder: relu(Pb + Qb) bf16, chunk j -> A buffer p ----
    auto build_A = [&](int j, int p) {
        char* ab = dsm + OFF_A(p);
        const int kb = j * 128 + cc * 8;
        uint2 q = *reinterpret_cast<const uint2*>(dsm + OFF_QB + hi * 1024 + kb);
        #pragma unroll
        for (int pass = 0; pass < 8; pass++) {
            int pr = pass * 2 + prb;
            uint2 pv = *reinterpret_cast<const uint2*>(dsm + OFF_PB + pr * 1024 + kb);
            uint2 u;
            u.x = bf2_addrelu(pv.x, q.x);
            u.y = bf2_addrelu(pv.y, q.y);
            *reinterpret_cast<uint2*>(ab + (pass * 16 + tg16) * ASTRIDE + cc * 8) = u;
        }
    };

    // ---- prologue: stage all of Pb/Qb + B(0) ----
    {
        #pragma unroll
        for (int i = 0; i < 4; i++) {           // Pb: 1024 x 16B
            int o = i * 256 + tid;
            int row = o >> 6, ch = o & 63;
            cp16(smb + OFF_PB + (uint32_t)o * 16,
                 g_Pb + ((size_t)(dblk * 16 + row) * BSZN + b) * 1024 + (size_t)ch * 16);
        }
        #pragma unroll
        for (int i = 0; i < 2; i++) {           // Qb: 512 x 16B
            int o = i * 256 + tid;
            int row = o >> 6, ch = o & 63;
            cp16(smb + OFF_QB + (uint32_t)o * 16,
                 g_Qb + ((size_t)(hblk * 8 + row) * BSZN + b) * 1024 + (size_t)ch * 16);
        }
        CP_COMMIT();
        issue_B(0, 0);
        CP_WAIT0();
        __syncthreads();
        build_A(0, 0);
    }

    // ---- mainloop: ONE sync per chunk ----
    #pragma unroll 1
    for (int j = 0; j < 8; j++) {
        const int cur = j & 1;
        __syncthreads();   // A(j) + B(j) visible; A buffer (j+1)&1 free
        if (j < 7) {
            issue_B(j + 1, cur ^ 1);
            build_A(j + 1, cur ^ 1);   // overlaps the B cp.async
        }

        const uint32_t AsB = smb + OFF_A(cur);
        const uint32_t BsB = smb + OFF_B(cur);
        #pragma unroll
        for (int ks = 0; ks < 4; ks++) {
            uint32_t a[4][4];
            #pragma unroll
            for (int mf = 0; mf < 4; mf++)
                ldsm_x4(a[mf], AsB + (uint32_t)(wm * 64 + mf * 16) * ASTRIDE
                                     + aRowOff + ks * 32);
            uint32_t bb[8];
            ldsm_x4(&bb[0], BsB + bOff + ks * 32);
            ldsm_x4(&bb[4], BsB + 16 * ASTRIDE + bOff + ks * 32);
            #pragma unroll
            for (int nf = 0; nf < 4; nf++)
                #pragma unroll
                for (int mf = 0; mf < 4; mf++)
                    mma_bf16(c[mf][nf], a[mf], &bb[nf * 2]);
        }

        if (j < 7) CP_WAIT0();  // B(j+1) landed; made visible by next sync
    }

    // ---- epilogue: two half-tiles of 64 rows via float staging buffer ----
    float* Ssm = reinterpret_cast<float*>(dsm + OFF_PB);   // 64*132 f = 33792B
    #pragma unroll 1
    for (int half = 0; half < 2; half++) {
        __syncthreads();
        if (wm == half) {
            #pragma unroll
            for (int mf = 0; mf < 4; mf++) {
                #pragma unroll
                for (int nf = 0; nf < 4; nf++) {
                    int rl = mf * 16 + g;
                    int col = wn * 32 + nf * 8 + 2 * tg;
                    *reinterpret_cast<float2*>(&Ssm[rl * 132 + col]) =
                        make_float2(c[mf][nf][0], c[mf][nf][1]);
                    *reinterpret_cast<float2*>(&Ssm[(rl + 8) * 132 + col]) =
                        make_float2(c[mf][nf][2], c[mf][nf][3]);
                }
            }
        }
        __syncthreads();
        #pragma unroll
        for (int i = 0; i < 8; i++) {
            int rl = wid * 8 + i;
            float4 v = *reinterpret_cast<const float4*>(&Ssm[rl * 132 + lane * 4]);
            v.x += bps[lane * 4 + 0];
            v.y += bps[lane * 4 + 1];
            v.z += bps[lane * 4 + 2];
            v.w += bps[lane * 4 + 3];
            float mx = fmaxf(fmaxf(v.x, v.y), fmaxf(v.z, v.w));
            #pragma unroll
            for (int off = 16; off > 0; off >>= 1)
                mx = fmaxf(mx, __shfl_xor_sync(0xffffffffu, mx, off));
            mx = fmaxf(mx, 0.f);  // nil column
            float se = __expf(v.x - mx) + __expf(v.y - mx) +
                       __expf(v.z - mx) + __expf(v.w - mx);
            #pragma unroll
            for (int off = 16; off > 0; off >>= 1)
                se += __shfl_xor_sync(0xffffffffu, se, off);
            se += __expf(-mx);  // nil column contribution
            float lse = mx + __logf(se);
            int row = half * 64 + rl;
            int d = dblk * 16 + (row >> 3);
            int h = hblk * 8 + (row & 7);
            float* op = out + (size_t)((d * BSZN + b) * HEADN + h) * (RELN + 1);
            if (lane == 0) op[0] = -lse;
            op[1 + lane * 4 + 0] = v.x - lse;
            op[1 + lane * 4 + 1] = v.y - lse;
            op[1 + lane * 4 + 2] = v.z - lse;
            op[1 + lane * 4 + 3] = v.w - lse;
        }
    }
}

// ---------------------------------------------------------------------------
extern "C" void kernel_launch(void* const* d_in, const int* in_sizes, int n_in,
                              void* d_out, int out_size) {
    const float* outs = (const float*)d_in[0];  // [96,16,512]
    const float* gs   = (const float*)d_in[1];  // [96,16,512]
    const float* Wt   = (const float*)d_in[2];  // [512,1024]
    const float* bt   = (const float*)d_in[3];  // [512]
    const float* Wp   = (const float*)d_in[4];  // [128,512]
    const float* bp   = (const float*)d_in[5];  // [128]
    float* out = (float*)d_out;                 // [96,16,96,129]

    (void)in_sizes; (void)n_in; (void)out_size;

    static bool attr_set = false;
    if (!attr_set) {
        cudaFuncSetAttribute(rel_kernel,
                             cudaFuncAttributeMaxDynamicSharedMemorySize,
                             REL_SMEM);
        attr_set = true;
    }

    wpb_kernel<<<RELN * DIMN / 4 / 256, 256>>>(Wp);      // 64 blocks

    dim3 pg(DIMN / 128, (DEPN * BSZN) / 128, 2);  // (4, 12, 2)
    proj_kernel<<<pg, 256>>>(outs, gs, Wt, bt);

    dim3 mg(HEADN / 8, DEPN / 16, BSZN);          // (12, 6, 16)
    rel_kernel<<<mg, 256, REL_SMEM>>>(bp, out);
}

// round 11
// speedup vs baseline: 2.0009x; 1.1126x over previous
#include <cuda_runtime.h>
#include <cuda_bf16.h>
#include <cstdint>
#include <cstddef>

#define DEPN  96
#define HEADN 96
#define BSZN  16
#define DIMN  512
#define RELN  128

// bf16 scratch
__device__ __align__(16) uint8_t g_Inb[2 * 1536 * DIMN * 2];   // outs rows 0..1535, gs rows 1536..
__device__ __align__(16) uint8_t g_Wtb[2 * DIMN * DIMN * 2];   // [which][e][k]
__device__ __align__(16) uint8_t g_Wpb[RELN * DIMN * 2];
__device__ __align__(16) uint8_t g_Pb[DEPN * BSZN * DIMN * 2]; // bf16(outs@Wt1 + bt)
__device__ __align__(16) uint8_t g_Qb[HEADN * BSZN * DIMN * 2];

// pack two floats -> bf16x2 (lo = first arg)
__device__ __forceinline__ uint32_t f2bf2(float lo, float hi) {
    uint32_t r;
    asm("cvt.rn.bf16x2.f32 %0, %1, %2;" : "=r"(r) : "f"(hi), "f"(lo));
    return r;
}

// relu(p + q) on bf16x2 pairs
__device__ __forceinline__ uint32_t bf2_addrelu(uint32_t p, uint32_t q) {
    uint32_t s, r;
    asm("add.rn.bf16x2 %0, %1, %2;" : "=r"(s) : "r"(p), "r"(q));
    asm("max.bf16x2 %0, %1, %2;" : "=r"(r) : "r"(s), "r"(0u));
    return r;
}

__device__ __forceinline__ uint32_t smem_u32(const void* p) {
    uint32_t a;
    asm("{ .reg .u64 t; cvta.to.shared.u64 t, %1; cvt.u32.u64 %0, t; }"
        : "=r"(a) : "l"(p));
    return a;
}

__device__ __forceinline__ void cp16(uint32_t dst, const void* src) {
    asm volatile("cp.async.cg.shared.global [%0], [%1], 16;"
        :: "r"(dst), "l"(src));
}
#define CP_COMMIT() asm volatile("cp.async.commit_group;" ::: "memory")
#define CP_WAIT0()  asm volatile("cp.async.wait_group 0;" ::: "memory")

__device__ __forceinline__ void ldsm_x4(uint32_t* r, uint32_t addr) {
    asm volatile("ldmatrix.sync.aligned.m8n8.x4.shared.b16 {%0,%1,%2,%3}, [%4];"
        : "=r"(r[0]), "=r"(r[1]), "=r"(r[2]), "=r"(r[3]) : "r"(addr));
}

__device__ __forceinline__ void mma_bf16(float* c, const uint32_t* a, const uint32_t* b) {
    asm volatile(
        "mma.sync.aligned.m16n8k16.row.col.f32.bf16.bf16.f32 "
        "{%0,%1,%2,%3}, {%4,%5,%6,%7}, {%8,%9}, {%0,%1,%2,%3};\n"
        : "+f"(c[0]), "+f"(c[1]), "+f"(c[2]), "+f"(c[3])
        : "r"(a[0]), "r"(a[1]), "r"(a[2]), "r"(a[3]), "r"(b[0]), "r"(b[1]));
}

#define ASTRIDE 144    // 128B data + 16B pad per smem row (conflict-free ldmatrix)

// ---------------------------------------------------------------------------
// Kernel 0: fp32 -> bf16 conversion for outs, gs, Wt (reordered), Wp.
// One float4 per thread; 2112 blocks x 256.
// ---------------------------------------------------------------------------
#define R_OUTS 196608                 // 1536*512/4
#define R_GS   (R_OUTS + 196608)
#define R_WT   (R_GS + 131072)        // 2*512*512/4
#define R_WP   (R_WT + 16384)         // 128*512/4

__global__ void prep_kernel(const float* __restrict__ outs,
                            const float* __restrict__ gs,
                            const float* __restrict__ Wt,
                            const float* __restrict__ Wp)
{
    int o = blockIdx.x * 256 + threadIdx.x;
    float4 v;
    uint8_t* dst;
    if (o < R_OUTS) {
        v = reinterpret_cast<const float4*>(outs)[o];
        dst = g_Inb + (size_t)o * 8;
    } else if (o < R_GS) {
        int i = o - R_OUTS;
        v = reinterpret_cast<const float4*>(gs)[i];
        dst = g_Inb + (size_t)(R_OUTS + i) * 8;
    } else if (o < R_WT) {
        int d = o - R_GS;                 // [which][e][k4]
        int which = d >> 16;              // 65536 f4 per half
        int r = d & 65535;
        int e = r >> 7, k4 = r & 127;
        v = reinterpret_cast<const float4*>(Wt)[e * 256 + which * 128 + k4];
        dst = g_Wtb + (size_t)d * 8;
    } else {
        int i = o - R_WT;
        v = reinterpret_cast<const float4*>(Wp)[i];
        dst = g_Wpb + (size_t)i * 8;
    }
    uint2 u;
    u.x = f2bf2(v.x, v.y);
    u.y = f2bf2(v.z, v.w);
    *reinterpret_cast<uint2*>(dst) = u;
}

// ---------------------------------------------------------------------------
// Kernel 1: projections, pure bf16 GEMM (clone of rel's MMA core).
// Block: 128 rows (of 1536) x 128 e-cols, K=512 in 8 chunks of 64.
// which=0: P = outs@Wt1 + bt -> g_Pb.  which=1: Q = gs@Wt2 -> g_Qb.
// ---------------------------------------------------------------------------
#define PJ_A(s) ((s) * 18432)
#define PJ_B(s) (36864 + (s) * 18432)
#define PJ_SMEM 73728

__global__ __launch_bounds__(256, 2)
void projb_kernel(const float* __restrict__ bt)
{
    extern __shared__ __align__(16) char dsm[];
    const uint32_t smb = smem_u32(dsm);

    const int which = blockIdx.z;
    const int m0 = blockIdx.y * 128;
    const int e0 = blockIdx.x * 128;
    const uint8_t* Arows = g_Inb + (size_t)which * 1536 * (DIMN * 2);
    const uint8_t* Brows = g_Wtb + (size_t)which * DIMN * (DIMN * 2);

    const int tid = threadIdx.x;
    const int wid = tid >> 5;
    const int lane = tid & 31;
    const int wm = wid >> 2;
    const int wn = wid & 3;
    const int g = lane >> 2;
    const int tg = lane & 3;

    float c[4][4][4];
    #pragma unroll
    for (int i = 0; i < 4; i++)
        #pragma unroll
        for (int j = 0; j < 4; j++)
            #pragma unroll
            for (int k = 0; k < 4; k++) c[i][j][k] = 0.f;

    const uint32_t aRowOff = (uint32_t)(lane & 15) * ASTRIDE + (uint32_t)(lane >> 4) * 16;
    const uint32_t bRow = (uint32_t)(wn * 32 + ((lane >> 4) << 3) + (lane & 7));
    const uint32_t bOff = bRow * ASTRIDE + (uint32_t)((lane >> 3) & 1) * 16;

    auto issue = [&](int j, int s) {
        #pragma unroll
        for (int i = 0; i < 4; i++) {
            int o = i * 256 + tid;
            int n = o >> 3, ch = o & 7;
            cp16(smb + PJ_A(s) + (uint32_t)n * ASTRIDE + (uint32_t)ch * 16,
                 Arows + (size_t)(m0 + n) * (DIMN * 2) + (size_t)j * 128 + (size_t)ch * 16);
            cp16(smb + PJ_B(s) + (uint32_t)n * ASTRIDE + (uint32_t)ch * 16,
                 Brows + (size_t)(e0 + n) * (DIMN * 2) + (size_t)j * 128 + (size_t)ch * 16);
        }
        CP_COMMIT();
    };

    issue(0, 0);
    #pragma unroll 1
    for (int j = 0; j < 8; j++) {
        const int cur = j & 1;
        CP_WAIT0();
        __syncthreads();
        if (j < 7) issue(j + 1, cur ^ 1);

        const uint32_t AsB = smb + PJ_A(cur);
        const uint32_t BsB = smb + PJ_B(cur);
        #pragma unroll
        for (int ks = 0; ks < 4; ks++) {
            uint32_t a[4][4];
            #pragma unroll
            for (int mf = 0; mf < 4; mf++)
                ldsm_x4(a[mf], AsB + (uint32_t)(wm * 64 + mf * 16) * ASTRIDE
                                     + aRowOff + ks * 32);
            uint32_t bb[8];
            ldsm_x4(&bb[0], BsB + bOff + ks * 32);
            ldsm_x4(&bb[4], BsB + 16 * ASTRIDE + bOff + ks * 32);
            #pragma unroll
            for (int nf = 0; nf < 4; nf++)
                #pragma unroll
                for (int mf = 0; mf < 4; mf++)
                    mma_bf16(c[mf][nf], a[mf], &bb[nf * 2]);
        }
    }

    uint8_t* Outb = which ? g_Qb : g_Pb;
    #pragma unroll
    for (int mf = 0; mf < 4; mf++) {
        #pragma unroll
        for (int nf = 0; nf < 4; nf++) {
            int r = m0 + wm * 64 + mf * 16 + g;
            int col = e0 + wn * 32 + nf * 8 + 2 * tg;
            float b0 = 0.f, b1 = 0.f;
            if (!which) { b0 = bt[col]; b1 = bt[col + 1]; }
            *reinterpret_cast<uint32_t*>(Outb + ((size_t)r * DIMN + col) * 2) =
                f2bf2(c[mf][nf][0] + b0, c[mf][nf][1] + b1);
            *reinterpret_cast<uint32_t*>(Outb + ((size_t)(r + 8) * DIMN + col) * 2) =
                f2bf2(c[mf][nf][2] + b0, c[mf][nf][3] + b1);
        }
    }
}

// ---------------------------------------------------------------------------
// Kernel 2: fused pairwise scores + log-softmax.
// P/Q bf16 staged once; B double-buffered cp.async; A = relu(Pb+Qb) bf16,
// double-buffered; fragment-level software pipeline in the MMA loop;
// single-pass epilogue. Block = 128 rows (16 dep x 8 head) x 128 rel.
// ---------------------------------------------------------------------------
#define OFF_BPS 0
#define OFF_PB  1024
#define OFF_QB  (OFF_PB + 16384)
#define OFF_B(s) (25600 + (s) * (128 * ASTRIDE))
#define OFF_A(p) (25600 + 2 * 128 * ASTRIDE + (p) * (128 * ASTRIDE))
#define REL_SMEM (25600 + 4 * 128 * ASTRIDE)   // 99328 B

__global__ __launch_bounds__(256, 2)
void rel_kernel(const float* __restrict__ bp,
                float* __restrict__ out)
{
    extern __shared__ __align__(16) char dsm[];
    const uint32_t smb = smem_u32(dsm);
    float* bps = reinterpret_cast<float*>(dsm + OFF_BPS);

    const int hblk = blockIdx.x;  // 0..11
    const int dblk = blockIdx.y;  // 0..5
    const int b = blockIdx.z;     // 0..15

    const int tid = threadIdx.x;
    const int wid = tid >> 5;
    const int lane = tid & 31;
    const int wm = wid >> 2;
    const int wn = wid & 3;
    const int g = lane >> 2;
    const int tg = lane & 3;

    if (tid < RELN) bps[tid] = bp[tid];

    float c[4][4][4];
    #pragma unroll
    for (int i = 0; i < 4; i++)
        #pragma unroll
        for (int j = 0; j < 4; j++)
            #pragma unroll
            for (int k = 0; k < 4; k++) c[i][j][k] = 0.f;

    const int tg16 = tid >> 4;
    const int cc = tid & 15;
    const int hi = tg16 & 7;
    const int prb = tg16 >> 3;

    const uint32_t aRowOff = (uint32_t)(lane & 15) * ASTRIDE + (uint32_t)(lane >> 4) * 16;
    const uint32_t bRow = (uint32_t)(wn * 32 + ((lane >> 4) << 3) + (lane & 7));
    const uint32_t bOff = bRow * ASTRIDE + (uint32_t)((lane >> 3) & 1) * 16;

    auto issue_B = [&](int j, int s) {
        const uint32_t stb = smb + OFF_B(s);
        #pragma unroll
        for (int i = 0; i < 4; i++) {
            int o = i * 256 + tid;
            int n = o >> 3, ch = o & 7;
            cp16(stb + (uint32_t)n * ASTRIDE + (uint32_t)ch * 16,
                 g_Wpb + (size_t)n * (DIMN * 2) + (size_t)j * 128 + (size_t)ch * 16);
        }
        CP_COMMIT();
    };

    auto build_A = [&](int j, int p) {
        char* ab = dsm + OFF_A(p);
        const int kb = j * 128 + cc * 8;
        uint2 q = *reinterpret_cast<const uint2*>(dsm + OFF_QB + hi * 1024 + kb);
        #pragma unroll
        for (int pass = 0; pass < 8; pass++) {
            int pr = pass * 2 + prb;
            uint2 pv = *reinterpret_cast<const uint2*>(dsm + OFF_PB + pr * 1024 + kb);
            uint2 u;
            u.x = bf2_addrelu(pv.x, q.x);
            u.y = bf2_addrelu(pv.y, q.y);
            *reinterpret_cast<uint2*>(ab + (pass * 16 + tg16) * ASTRIDE + cc * 8) = u;
        }
    };

    // prologue: stage all of Pb/Qb + B(0)
    {
        #pragma unroll
        for (int i = 0; i < 4; i++) {
            int o = i * 256 + tid;
            int row = o >> 6, ch = o & 63;
            cp16(smb + OFF_PB + (uint32_t)o * 16,
                 g_Pb + ((size_t)(dblk * 16 + row) * BSZN + b) * 1024 + (size_t)ch * 16);
        }
        #pragma unroll
        for (int i = 0; i < 2; i++) {
            int o = i * 256 + tid;
            int row = o >> 6, ch = o & 63;
            cp16(smb + OFF_QB + (uint32_t)o * 16,
                 g_Qb + ((size_t)(hblk * 8 + row) * BSZN + b) * 1024 + (size_t)ch * 16);
        }
        CP_COMMIT();
        issue_B(0, 0);
        CP_WAIT0();
        __syncthreads();
        build_A(0, 0);
    }

    // mainloop: one sync per chunk; fragment-pipelined MMA phase
    #pragma unroll 1
    for (int j = 0; j < 8; j++) {
        const int cur = j & 1;
        __syncthreads();
        if (j < 7) {
            issue_B(j + 1, cur ^ 1);
            build_A(j + 1, cur ^ 1);
        }

        const uint32_t AsB = smb + OFF_A(cur);
        const uint32_t BsB = smb + OFF_B(cur);
        uint32_t a[2][16], bb[2][8];
        #pragma unroll
        for (int mf = 0; mf < 4; mf++)
            ldsm_x4(&a[0][mf * 4], AsB + (uint32_t)(wm * 64 + mf * 16) * ASTRIDE + aRowOff);
        ldsm_x4(&bb[0][0], BsB + bOff);
        ldsm_x4(&bb[0][4], BsB + 16 * ASTRIDE + bOff);
        #pragma unroll
        for (int ks = 0; ks < 4; ks++) {
            const int cu = ks & 1, nx = cu ^ 1;
            if (ks < 3) {
                #pragma unroll
                for (int mf = 0; mf < 4; mf++)
                    ldsm_x4(&a[nx][mf * 4],
                            AsB + (uint32_t)(wm * 64 + mf * 16) * ASTRIDE
                                + aRowOff + (ks + 1) * 32);
                ldsm_x4(&bb[nx][0], BsB + bOff + (ks + 1) * 32);
                ldsm_x4(&bb[nx][4], BsB + 16 * ASTRIDE + bOff + (ks + 1) * 32);
            }
            #pragma unroll
            for (int nf = 0; nf < 4; nf++)
                #pragma unroll
                for (int mf = 0; mf < 4; mf++)
                    mma_bf16(c[mf][nf], &a[cu][mf * 4], &bb[cu][nf * 2]);
        }

        if (j < 7) CP_WAIT0();
    }

    // single-pass epilogue: stage all 128 rows, then per-row log-softmax
    float* Ssm = reinterpret_cast<float*>(dsm + 1024);   // 128 x 132 floats
    __syncthreads();   // all MMA smem reads done before overwrite
    #pragma unroll
    for (int mf = 0; mf < 4; mf++) {
        #pragma unroll
        for (int nf = 0; nf < 4; nf++) {
            int rl = wm * 64 + mf * 16 + g;
            int col = wn * 32 + nf * 8 + 2 * tg;
            *reinterpret_cast<float2*>(&Ssm[rl * 132 + col]) =
                make_float2(c[mf][nf][0], c[mf][nf][1]);
            *reinterpret_cast<float2*>(&Ssm[(rl + 8) * 132 + col]) =
                make_float2(c[mf][nf][2], c[mf][nf][3]);
        }
    }
    __syncthreads();
    #pragma unroll
    for (int i = 0; i < 16; i++) {
        int rl = wid * 16 + i;
        float4 v = *reinterpret_cast<const float4*>(&Ssm[rl * 132 + lane * 4]);
        v.x += bps[lane * 4 + 0];
        v.y += bps[lane * 4 + 1];
        v.z += bps[lane * 4 + 2];
        v.w += bps[lane * 4 + 3];
        float mx = fmaxf(fmaxf(v.x, v.y), fmaxf(v.z, v.w));
        #pragma unroll
        for (int off = 16; off > 0; off >>= 1)
            mx = fmaxf(mx, __shfl_xor_sync(0xffffffffu, mx, off));
        mx = fmaxf(mx, 0.f);  // nil column
        float se = __expf(v.x - mx) + __expf(v.y - mx) +
                   __expf(v.z - mx) + __expf(v.w - mx);
        #pragma unroll
        for (int off = 16; off > 0; off >>= 1)
            se += __shfl_xor_sync(0xffffffffu, se, off);
        se += __expf(-mx);  // nil column contribution
        float lse = mx + __logf(se);
        int d = dblk * 16 + (rl >> 3);
        int h = hblk * 8 + (rl & 7);
        float* op = out + (size_t)((d * BSZN + b) * HEADN + h) * (RELN + 1);
        if (lane == 0) op[0] = -lse;
        op[1 + lane * 4 + 0] = v.x - lse;
        op[1 + lane * 4 + 1] = v.y - lse;
        op[1 + lane * 4 + 2] = v.z - lse;
        op[1 + lane * 4 + 3] = v.w - lse;
    }
}

// ---------------------------------------------------------------------------
extern "C" void kernel_launch(void* const* d_in, const int* in_sizes, int n_in,
                              void* d_out, int out_size) {
    const float* outs = (const float*)d_in[0];  // [96,16,512]
    const float* gs   = (const float*)d_in[1];  // [96,16,512]
    const float* Wt   = (const float*)d_in[2];  // [512,1024]
    const float* bt   = (const float*)d_in[3];  // [512]
    const float* Wp   = (const float*)d_in[4];  // [128,512]
    const float* bp   = (const float*)d_in[5];  // [128]
    float* out = (float*)d_out;                 // [96,16,96,129]

    (void)in_sizes; (void)n_in; (void)out_size;

    static bool attr_set = false;
    if (!attr_set) {
        cudaFuncSetAttribute(rel_kernel,
                             cudaFuncAttributeMaxDynamicSharedMemorySize,
                             REL_SMEM);
        cudaFuncSetAttribute(projb_kernel,
                             cudaFuncAttributeMaxDynamicSharedMemorySize,
                             PJ_SMEM);
        attr_set = true;
    }

    prep_kernel<<<R_WP / 256, 256>>>(outs, gs, Wt, Wp);        // 2112 blocks

    dim3 pg(DIMN / 128, 1536 / 128, 2);           // (4, 12, 2)
    projb_kernel<<<pg, 256, PJ_SMEM>>>(bt);

    dim3 mg(HEADN / 8, DEPN / 16, BSZN);          // (12, 6, 16)
    rel_kernel<<<mg, 256, REL_SMEM>>>(bp, out);
}

// round 13
// speedup vs baseline: 2.0460x; 1.0225x over previous
#include <cuda_runtime.h>
#include <cuda_bf16.h>
#include <cstdint>
#include <cstddef>

#define DEPN  96
#define HEADN 96
#define BSZN  16
#define DIMN  512
#define RELN  128

// bf16 scratch
__device__ __align__(16) uint8_t g_Inb[2 * 1536 * DIMN * 2];   // outs rows 0..1535, gs rows 1536..
__device__ __align__(16) uint8_t g_Wtb[2 * DIMN * DIMN * 2];   // [which][e][k]
__device__ __align__(16) uint8_t g_Wpb[RELN * DIMN * 2];
__device__ __align__(16) uint8_t g_Pb[DEPN * BSZN * DIMN * 2]; // bf16(outs@Wt1 + bt)
__device__ __align__(16) uint8_t g_Qb[HEADN * BSZN * DIMN * 2];

// pack two floats -> bf16x2 (lo = first arg)
__device__ __forceinline__ uint32_t f2bf2(float lo, float hi) {
    uint32_t r;
    asm("cvt.rn.bf16x2.f32 %0, %1, %2;" : "=r"(r) : "f"(hi), "f"(lo));
    return r;
}

// relu(p + q) on bf16x2 pairs
__device__ __forceinline__ uint32_t bf2_addrelu(uint32_t p, uint32_t q) {
    uint32_t s, r;
    asm("add.rn.bf16x2 %0, %1, %2;" : "=r"(s) : "r"(p), "r"(q));
    asm("max.bf16x2 %0, %1, %2;" : "=r"(r) : "r"(s), "r"(0u));
    return r;
}

__device__ __forceinline__ uint32_t smem_u32(const void* p) {
    uint32_t a;
    asm("{ .reg .u64 t; cvta.to.shared.u64 t, %1; cvt.u32.u64 %0, t; }"
        : "=r"(a) : "l"(p));
    return a;
}

__device__ __forceinline__ void cp16(uint32_t dst, const void* src) {
    asm volatile("cp.async.cg.shared.global [%0], [%1], 16;"
        :: "r"(dst), "l"(src));
}
#define CP_COMMIT() asm volatile("cp.async.commit_group;" ::: "memory")
#define CP_WAIT0()  asm volatile("cp.async.wait_group 0;" ::: "memory")

__device__ __forceinline__ uint32_t lds32(uint32_t addr) {
    uint32_t v;
    asm volatile("ld.shared.b32 %0, [%1];" : "=r"(v) : "r"(addr));
    return v;
}

__device__ __forceinline__ void ldsm_x4(uint32_t* r, uint32_t addr) {
    asm volatile("ldmatrix.sync.aligned.m8n8.x4.shared.b16 {%0,%1,%2,%3}, [%4];"
        : "=r"(r[0]), "=r"(r[1]), "=r"(r[2]), "=r"(r[3]) : "r"(addr));
}

__device__ __forceinline__ void mma_bf16(float* c, const uint32_t* a, const uint32_t* b) {
    asm volatile(
        "mma.sync.aligned.m16n8k16.row.col.f32.bf16.bf16.f32 "
        "{%0,%1,%2,%3}, {%4,%5,%6,%7}, {%8,%9}, {%0,%1,%2,%3};\n"
        : "+f"(c[0]), "+f"(c[1]), "+f"(c[2]), "+f"(c[3])
        : "r"(a[0]), "r"(a[1]), "r"(a[2]), "r"(a[3]), "r"(b[0]), "r"(b[1]));
}

#define ASTRIDE 144    // 128B data + 16B pad per smem row (conflict-free ldmatrix)

// ---------------------------------------------------------------------------
// Kernel 0: fp32 -> bf16 conversion for outs, gs, Wt (reordered), Wp.
// ---------------------------------------------------------------------------
#define R_OUTS 196608                 // 1536*512/4
#define R_GS   (R_OUTS + 196608)
#define R_WT   (R_GS + 131072)        // 2*512*512/4
#define R_WP   (R_WT + 16384)         // 128*512/4

__global__ void prep_kernel(const float* __restrict__ outs,
                            const float* __restrict__ gs,
                            const float* __restrict__ Wt,
                            const float* __restrict__ Wp)
{
    int o = blockIdx.x * 256 + threadIdx.x;
    float4 v;
    uint8_t* dst;
    if (o < R_OUTS) {
        v = reinterpret_cast<const float4*>(outs)[o];
        dst = g_Inb + (size_t)o * 8;
    } else if (o < R_GS) {
        int i = o - R_OUTS;
        v = reinterpret_cast<const float4*>(gs)[i];
        dst = g_Inb + (size_t)(R_OUTS + i) * 8;
    } else if (o < R_WT) {
        int d = o - R_GS;                 // [which][e][k4]
        int which = d >> 16;
        int r = d & 65535;
        int e = r >> 7, k4 = r & 127;
        v = reinterpret_cast<const float4*>(Wt)[e * 256 + which * 128 + k4];
        dst = g_Wtb + (size_t)d * 8;
    } else {
        int i = o - R_WT;
        v = reinterpret_cast<const float4*>(Wp)[i];
        dst = g_Wpb + (size_t)i * 8;
    }
    uint2 u;
    u.x = f2bf2(v.x, v.y);
    u.y = f2bf2(v.z, v.w);
    *reinterpret_cast<uint2*>(dst) = u;
}

// ---------------------------------------------------------------------------
// Kernel 1: projections, pure bf16 GEMM (unchanged from R11).
// ---------------------------------------------------------------------------
#define PJ_A(s) ((s) * 18432)
#define PJ_B(s) (36864 + (s) * 18432)
#define PJ_SMEM 73728

__global__ __launch_bounds__(256, 2)
void projb_kernel(const float* __restrict__ bt)
{
    extern __shared__ __align__(16) char dsm[];
    const uint32_t smb = smem_u32(dsm);

    const int which = blockIdx.z;
    const int m0 = blockIdx.y * 128;
    const int e0 = blockIdx.x * 128;
    const uint8_t* Arows = g_Inb + (size_t)which * 1536 * (DIMN * 2);
    const uint8_t* Brows = g_Wtb + (size_t)which * DIMN * (DIMN * 2);

    const int tid = threadIdx.x;
    const int wid = tid >> 5;
    const int lane = tid & 31;
    const int wm = wid >> 2;
    const int wn = wid & 3;
    const int g = lane >> 2;
    const int tg = lane & 3;

    float c[4][4][4];
    #pragma unroll
    for (int i = 0; i < 4; i++)
        #pragma unroll
        for (int j = 0; j < 4; j++)
            #pragma unroll
            for (int k = 0; k < 4; k++) c[i][j][k] = 0.f;

    const uint32_t aRowOff = (uint32_t)(lane & 15) * ASTRIDE + (uint32_t)(lane >> 4) * 16;
    const uint32_t bRow = (uint32_t)(wn * 32 + ((lane >> 4) << 3) + (lane & 7));
    const uint32_t bOff = bRow * ASTRIDE + (uint32_t)((lane >> 3) & 1) * 16;

    auto issue = [&](int j, int s) {
        #pragma unroll
        for (int i = 0; i < 4; i++) {
            int o = i * 256 + tid;
            int n = o >> 3, ch = o & 7;
            cp16(smb + PJ_A(s) + (uint32_t)n * ASTRIDE + (uint32_t)ch * 16,
                 Arows + (size_t)(m0 + n) * (DIMN * 2) + (size_t)j * 128 + (size_t)ch * 16);
            cp16(smb + PJ_B(s) + (uint32_t)n * ASTRIDE + (uint32_t)ch * 16,
                 Brows + (size_t)(e0 + n) * (DIMN * 2) + (size_t)j * 128 + (size_t)ch * 16);
        }
        CP_COMMIT();
    };

    issue(0, 0);
    #pragma unroll 1
    for (int j = 0; j < 8; j++) {
        const int cur = j & 1;
        CP_WAIT0();
        __syncthreads();
        if (j < 7) issue(j + 1, cur ^ 1);

        const uint32_t AsB = smb + PJ_A(cur);
        const uint32_t BsB = smb + PJ_B(cur);
        #pragma unroll
        for (int ks = 0; ks < 4; ks++) {
            uint32_t a[4][4];
            #pragma unroll
            for (int mf = 0; mf < 4; mf++)
                ldsm_x4(a[mf], AsB + (uint32_t)(wm * 64 + mf * 16) * ASTRIDE
                                     + aRowOff + ks * 32);
            uint32_t bb[8];
            ldsm_x4(&bb[0], BsB + bOff + ks * 32);
            ldsm_x4(&bb[4], BsB + 16 * ASTRIDE + bOff + ks * 32);
            #pragma unroll
            for (int nf = 0; nf < 4; nf++)
                #pragma unroll
                for (int mf = 0; mf < 4; mf++)
                    mma_bf16(c[mf][nf], a[mf], &bb[nf * 2]);
        }
    }

    uint8_t* Outb = which ? g_Qb : g_Pb;
    #pragma unroll
    for (int mf = 0; mf < 4; mf++) {
        #pragma unroll
        for (int nf = 0; nf < 4; nf++) {
            int r = m0 + wm * 64 + mf * 16 + g;
            int col = e0 + wn * 32 + nf * 8 + 2 * tg;
            float b0 = 0.f, b1 = 0.f;
            if (!which) { b0 = bt[col]; b1 = bt[col + 1]; }
            *reinterpret_cast<uint32_t*>(Outb + ((size_t)r * DIMN + col) * 2) =
                f2bf2(c[mf][nf][0] + b0, c[mf][nf][1] + b1);
            *reinterpret_cast<uint32_t*>(Outb + ((size_t)(r + 8) * DIMN + col) * 2) =
                f2bf2(c[mf][nf][2] + b0, c[mf][nf][3] + b1);
        }
    }
}

// ---------------------------------------------------------------------------
// Kernel 2: fused pairwise scores + log-softmax, register-direct A fragments.
// P (16x512, stride 1024) and Q (8x512, stride 1040 -> conflict-free) staged
// once; A fragments built in regs: a = relu(P2[pr][kp] + Q2[g][kp]) where the
// P row is lane-invariant (broadcast LDS) and Q row = g. NO smem A tile.
// B double-buffered via cp.async; one __syncthreads per chunk (gates B only).
// ---------------------------------------------------------------------------
#define QSTRIDE 1040
#define OFF_BPS 0
#define OFF_PB  1024                        // 16 x 1024 = 16384
#define OFF_QB  (OFF_PB + 16384)            // 8 x 1040 = 8320 -> ends 25728
#define OFF_B(s) (25728 + (s) * (128 * ASTRIDE))
#define REL_SMEM 68608                      // epilogue Ssm: 1024 + 128*132*4

__global__ __launch_bounds__(256, 2)
void rel_kernel(const float* __restrict__ bp,
                float* __restrict__ out)
{
    extern __shared__ __align__(16) char dsm[];
    const uint32_t smb = smem_u32(dsm);
    float* bps = reinterpret_cast<float*>(dsm + OFF_BPS);

    const int hblk = blockIdx.x;  // 0..11
    const int dblk = blockIdx.y;  // 0..5
    const int b = blockIdx.z;     // 0..15

    const int tid = threadIdx.x;
    const int wid = tid >> 5;
    const int lane = tid & 31;
    const int wm = wid >> 2;
    const int wn = wid & 3;
    const int g = lane >> 2;
    const int tg = lane & 3;

    if (tid < RELN) bps[tid] = bp[tid];

    float c[4][4][4];
    #pragma unroll
    for (int i = 0; i < 4; i++)
        #pragma unroll
        for (int j = 0; j < 4; j++)
            #pragma unroll
            for (int k = 0; k < 4; k++) c[i][j][k] = 0.f;

    // per-thread constant addresses for fragment-direct A build
    const uint32_t qbase = smb + OFF_QB + (uint32_t)g * QSTRIDE + (uint32_t)tg * 4;
    const uint32_t pbase = smb + OFF_PB + (uint32_t)(wm * 8) * 1024 + (uint32_t)tg * 4;

    // B ldmatrix per-lane pieces (as in R11, proven)
    const uint32_t bRow = (uint32_t)(wn * 32 + ((lane >> 4) << 3) + (lane & 7));
    const uint32_t bOff = bRow * ASTRIDE + (uint32_t)((lane >> 3) & 1) * 16;

    auto issue_B = [&](int j, int s) {
        const uint32_t stb = smb + OFF_B(s);
        #pragma unroll
        for (int i = 0; i < 4; i++) {
            int o = i * 256 + tid;
            int n = o >> 3, ch = o & 7;
            cp16(stb + (uint32_t)n * ASTRIDE + (uint32_t)ch * 16,
                 g_Wpb + (size_t)n * (DIMN * 2) + (size_t)j * 128 + (size_t)ch * 16);
        }
        CP_COMMIT();
    };

    // prologue: stage P (stride 1024), Q (stride 1040), B(0)
    {
        #pragma unroll
        for (int i = 0; i < 4; i++) {
            int o = i * 256 + tid;
            int row = o >> 6, ch = o & 63;
            cp16(smb + OFF_PB + (uint32_t)row * 1024 + (uint32_t)ch * 16,
                 g_Pb + ((size_t)(dblk * 16 + row) * BSZN + b) * 1024 + (size_t)ch * 16);
        }
        #pragma unroll
        for (int i = 0; i < 2; i++) {
            int o = i * 256 + tid;
            int row = o >> 6, ch = o & 63;
            cp16(smb + OFF_QB + (uint32_t)row * QSTRIDE + (uint32_t)ch * 16,
                 g_Qb + ((size_t)(hblk * 8 + row) * BSZN + b) * 1024 + (size_t)ch * 16);
        }
        CP_COMMIT();
        issue_B(0, 0);
        CP_WAIT0();
    }

    // mainloop: one sync per chunk (B visibility + B-stage reuse guard)
    #pragma unroll 1
    for (int j = 0; j < 8; j++) {
        const int cur = j & 1;
        __syncthreads();                // B(j) visible; stage cur^1 reads done
        if (j < 7) issue_B(j + 1, cur ^ 1);

        const uint32_t BsB = smb + OFF_B(cur);
        const uint32_t kchunk = (uint32_t)j * 128;   // byte offset of chunk in P/Q rows
        uint32_t bb[2][8];
        ldsm_x4(&bb[0][0], BsB + bOff);
        ldsm_x4(&bb[0][4], BsB + 16 * ASTRIDE + bOff);
        #pragma unroll
        for (int ks = 0; ks < 4; ks++) {
            const int cu = ks & 1, nx = cu ^ 1;
            if (ks < 3) {
                ldsm_x4(&bb[nx][0], BsB + bOff + (ks + 1) * 32);
                ldsm_x4(&bb[nx][4], BsB + 16 * ASTRIDE + bOff + (ks + 1) * 32);
            }
            const uint32_t q0 = lds32(qbase + kchunk + ks * 32);
            const uint32_t q1 = lds32(qbase + kchunk + ks * 32 + 16);
            #pragma unroll
            for (int mf = 0; mf < 4; mf++) {
                const uint32_t pb = pbase + (uint32_t)mf * 2048 + kchunk + ks * 32;
                uint32_t p00 = lds32(pb);
                uint32_t p10 = lds32(pb + 1024);
                uint32_t p01 = lds32(pb + 16);
                uint32_t p11 = lds32(pb + 1024 + 16);
                uint32_t a[4];
                a[0] = bf2_addrelu(p00, q0);
                a[1] = bf2_addrelu(p10, q0);
                a[2] = bf2_addrelu(p01, q1);
                a[3] = bf2_addrelu(p11, q1);
                #pragma unroll
                for (int nf = 0; nf < 4; nf++)
                    mma_bf16(c[mf][nf], a, &bb[cu][nf * 2]);
            }
        }

        if (j < 7) CP_WAIT0();
    }

    // single-pass epilogue: stage 128x132, per-row log-softmax
    float* Ssm = reinterpret_cast<float*>(dsm + 1024);
    __syncthreads();
    #pragma unroll
    for (int mf = 0; mf < 4; mf++) {
        #pragma unroll
        for (int nf = 0; nf < 4; nf++) {
            int rl = wm * 64 + mf * 16 + g;
            int col = wn * 32 + nf * 8 + 2 * tg;
            *reinterpret_cast<float2*>(&Ssm[rl * 132 + col]) =
                make_float2(c[mf][nf][0], c[mf][nf][1]);
            *reinterpret_cast<float2*>(&Ssm[(rl + 8) * 132 + col]) =
                make_float2(c[mf][nf][2], c[mf][nf][3]);
        }
    }
    __syncthreads();
    #pragma unroll
    for (int i = 0; i < 16; i++) {
        int rl = wid * 16 + i;
        float4 v = *reinterpret_cast<const float4*>(&Ssm[rl * 132 + lane * 4]);
        v.x += bps[lane * 4 + 0];
        v.y += bps[lane * 4 + 1];
        v.z += bps[lane * 4 + 2];
        v.w += bps[lane * 4 + 3];
        float mx = fmaxf(fmaxf(v.x, v.y), fmaxf(v.z, v.w));
        #pragma unroll
        for (int off = 16; off > 0; off >>= 1)
            mx = fmaxf(mx, __shfl_xor_sync(0xffffffffu, mx, off));
        mx = fmaxf(mx, 0.f);  // nil column
        float se = __expf(v.x - mx) + __expf(v.y - mx) +
                   __expf(v.z - mx) + __expf(v.w - mx);
        #pragma unroll
        for (int off = 16; off > 0; off >>= 1)
            se += __shfl_xor_sync(0xffffffffu, se, off);
        se += __expf(-mx);  // nil column contribution
        float lse = mx + __logf(se);
        int d = dblk * 16 + (rl >> 3);
        int h = hblk * 8 + (rl & 7);
        float* op = out + (size_t)((d * BSZN + b) * HEADN + h) * (RELN + 1);
        if (lane == 0) op[0] = -lse;
        op[1 + lane * 4 + 0] = v.x - lse;
        op[1 + lane * 4 + 1] = v.y - lse;
        op[1 + lane * 4 + 2] = v.z - lse;
        op[1 + lane * 4 + 3] = v.w - lse;
    }
}

// ---------------------------------------------------------------------------
extern "C" void kernel_launch(void* const* d_in, const int* in_sizes, int n_in,
                              void* d_out, int out_size) {
    const float* outs = (const float*)d_in[0];  // [96,16,512]
    const float* gs   = (const float*)d_in[1];  // [96,16,512]
    const float* Wt   = (const float*)d_in[2];  // [512,1024]
    const float* bt   = (const float*)d_in[3];  // [512]
    const float* Wp   = (const float*)d_in[4];  // [128,512]
    const float* bp   = (const float*)d_in[5];  // [128]
    float* out = (float*)d_out;                 // [96,16,96,129]

    (void)in_sizes; (void)n_in; (void)out_size;

    static bool attr_set = false;
    if (!attr_set) {
        cudaFuncSetAttribute(rel_kernel,
                             cudaFuncAttributeMaxDynamicSharedMemorySize,
                             REL_SMEM);
        cudaFuncSetAttribute(projb_kernel,
                             cudaFuncAttributeMaxDynamicSharedMemorySize,
                             PJ_SMEM);
        attr_set = true;
    }

    prep_kernel<<<R_WP / 256, 256>>>(outs, gs, Wt, Wp);        // 2112 blocks

    dim3 pg(DIMN / 128, 1536 / 128, 2);           // (4, 12, 2)
    projb_kernel<<<pg, 256, PJ_SMEM>>>(bt);

    dim3 mg(HEADN / 8, DEPN / 16, BSZN);          // (12, 6, 16)
    rel_kernel<<<mg, 256, REL_SMEM>>>(bp, out);
}

// round 14
// speedup vs baseline: 2.0558x; 1.0048x over previous
#include <cuda_runtime.h>
#include <cuda_bf16.h>
#include <cstdint>
#include <cstddef>

#define DEPN  96
#define HEADN 96
#define BSZN  16
#define DIMN  512
#define RELN  128

// bf16 scratch
__device__ __align__(16) uint8_t g_Inb[2 * 1536 * DIMN * 2];   // outs rows 0..1535, gs rows 1536..
__device__ __align__(16) uint8_t g_Wtb[2 * DIMN * DIMN * 2];   // [which][e][k]
__device__ __align__(16) uint8_t g_Wpb[RELN * DIMN * 2];
// P/Q stored with per-32B-block word permutation perm(w)=2*(w&3)+(w>>2)
__device__ __align__(16) uint8_t g_Pb[DEPN * BSZN * DIMN * 2]; // bf16(outs@Wt1 + bt)
__device__ __align__(16) uint8_t g_Qb[HEADN * BSZN * DIMN * 2];

// pack two floats -> bf16x2 (lo = first arg)
__device__ __forceinline__ uint32_t f2bf2(float lo, float hi) {
    uint32_t r;
    asm("cvt.rn.bf16x2.f32 %0, %1, %2;" : "=r"(r) : "f"(hi), "f"(lo));
    return r;
}

// relu(p + q) on bf16x2 pairs
__device__ __forceinline__ uint32_t bf2_addrelu(uint32_t p, uint32_t q) {
    uint32_t s, r;
    asm("add.rn.bf16x2 %0, %1, %2;" : "=r"(s) : "r"(p), "r"(q));
    asm("max.bf16x2 %0, %1, %2;" : "=r"(r) : "r"(s), "r"(0u));
    return r;
}

__device__ __forceinline__ uint32_t smem_u32(const void* p) {
    uint32_t a;
    asm("{ .reg .u64 t; cvta.to.shared.u64 t, %1; cvt.u32.u64 %0, t; }"
        : "=r"(a) : "l"(p));
    return a;
}

__device__ __forceinline__ void cp16(uint32_t dst, const void* src) {
    asm volatile("cp.async.cg.shared.global [%0], [%1], 16;"
        :: "r"(dst), "l"(src));
}
#define CP_COMMIT() asm volatile("cp.async.commit_group;" ::: "memory")
#define CP_WAIT0()  asm volatile("cp.async.wait_group 0;" ::: "memory")

__device__ __forceinline__ uint2 lds64(uint32_t addr) {
    uint2 v;
    asm volatile("ld.shared.v2.b32 {%0,%1}, [%2];" : "=r"(v.x), "=r"(v.y) : "r"(addr));
    return v;
}

__device__ __forceinline__ void ldsm_x4(uint32_t* r, uint32_t addr) {
    asm volatile("ldmatrix.sync.aligned.m8n8.x4.shared.b16 {%0,%1,%2,%3}, [%4];"
        : "=r"(r[0]), "=r"(r[1]), "=r"(r[2]), "=r"(r[3]) : "r"(addr));
}

__device__ __forceinline__ void mma_bf16(float* c, const uint32_t* a, const uint32_t* b) {
    asm volatile(
        "mma.sync.aligned.m16n8k16.row.col.f32.bf16.bf16.f32 "
        "{%0,%1,%2,%3}, {%4,%5,%6,%7}, {%8,%9}, {%0,%1,%2,%3};\n"
        : "+f"(c[0]), "+f"(c[1]), "+f"(c[2]), "+f"(c[3])
        : "r"(a[0]), "r"(a[1]), "r"(a[2]), "r"(a[3]), "r"(b[0]), "r"(b[1]));
}

#define ASTRIDE 144    // 128B data + 16B pad per smem row (conflict-free ldmatrix)

// ---------------------------------------------------------------------------
// Kernel 0: fp32 -> bf16 conversion for outs, gs, Wt (reordered), Wp.
// ---------------------------------------------------------------------------
#define R_OUTS 196608                 // 1536*512/4
#define R_GS   (R_OUTS + 196608)
#define R_WT   (R_GS + 131072)        // 2*512*512/4
#define R_WP   (R_WT + 16384)         // 128*512/4

__global__ void prep_kernel(const float* __restrict__ outs,
                            const float* __restrict__ gs,
                            const float* __restrict__ Wt,
                            const float* __restrict__ Wp)
{
    int o = blockIdx.x * 256 + threadIdx.x;
    float4 v;
    uint8_t* dst;
    if (o < R_OUTS) {
        v = reinterpret_cast<const float4*>(outs)[o];
        dst = g_Inb + (size_t)o * 8;
    } else if (o < R_GS) {
        int i = o - R_OUTS;
        v = reinterpret_cast<const float4*>(gs)[i];
        dst = g_Inb + (size_t)(R_OUTS + i) * 8;
    } else if (o < R_WT) {
        int d = o - R_GS;                 // [which][e][k4]
        int which = d >> 16;
        int r = d & 65535;
        int e = r >> 7, k4 = r & 127;
        v = reinterpret_cast<const float4*>(Wt)[e * 256 + which * 128 + k4];
        dst = g_Wtb + (size_t)d * 8;
    } else {
        int i = o - R_WT;
        v = reinterpret_cast<const float4*>(Wp)[i];
        dst = g_Wpb + (size_t)i * 8;
    }
    uint2 u;
    u.x = f2bf2(v.x, v.y);
    u.y = f2bf2(v.z, v.w);
    *reinterpret_cast<uint2*>(dst) = u;
}

// ---------------------------------------------------------------------------
// Kernel 1: projections, pure bf16 GEMM. Output rows written in the
// fragment-permuted word order: word w of each 32B block -> 2*(w&3)+(w>>2).
// ---------------------------------------------------------------------------
#define PJ_A(s) ((s) * 18432)
#define PJ_B(s) (36864 + (s) * 18432)
#define PJ_SMEM 73728

__global__ __launch_bounds__(256, 2)
void projb_kernel(const float* __restrict__ bt)
{
    extern __shared__ __align__(16) char dsm[];
    const uint32_t smb = smem_u32(dsm);

    const int which = blockIdx.z;
    const int m0 = blockIdx.y * 128;
    const int e0 = blockIdx.x * 128;
    const uint8_t* Arows = g_Inb + (size_t)which * 1536 * (DIMN * 2);
    const uint8_t* Brows = g_Wtb + (size_t)which * DIMN * (DIMN * 2);

    const int tid = threadIdx.x;
    const int wid = tid >> 5;
    const int lane = tid & 31;
    const int wm = wid >> 2;
    const int wn = wid & 3;
    const int g = lane >> 2;
    const int tg = lane & 3;

    float c[4][4][4];
    #pragma unroll
    for (int i = 0; i < 4; i++)
        #pragma unroll
        for (int j = 0; j < 4; j++)
            #pragma unroll
            for (int k = 0; k < 4; k++) c[i][j][k] = 0.f;

    const uint32_t aRowOff = (uint32_t)(lane & 15) * ASTRIDE + (uint32_t)(lane >> 4) * 16;
    const uint32_t bRow = (uint32_t)(wn * 32 + ((lane >> 4) << 3) + (lane & 7));
    const uint32_t bOff = bRow * ASTRIDE + (uint32_t)((lane >> 3) & 1) * 16;

    auto issue = [&](int j, int s) {
        #pragma unroll
        for (int i = 0; i < 4; i++) {
            int o = i * 256 + tid;
            int n = o >> 3, ch = o & 7;
            cp16(smb + PJ_A(s) + (uint32_t)n * ASTRIDE + (uint32_t)ch * 16,
                 Arows + (size_t)(m0 + n) * (DIMN * 2) + (size_t)j * 128 + (size_t)ch * 16);
            cp16(smb + PJ_B(s) + (uint32_t)n * ASTRIDE + (uint32_t)ch * 16,
                 Brows + (size_t)(e0 + n) * (DIMN * 2) + (size_t)j * 128 + (size_t)ch * 16);
        }
        CP_COMMIT();
    };

    issue(0, 0);
    #pragma unroll 1
    for (int j = 0; j < 8; j++) {
        const int cur = j & 1;
        CP_WAIT0();
        __syncthreads();
        if (j < 7) issue(j + 1, cur ^ 1);

        const uint32_t AsB = smb + PJ_A(cur);
        const uint32_t BsB = smb + PJ_B(cur);
        #pragma unroll
        for (int ks = 0; ks < 4; ks++) {
            uint32_t a[4][4];
            #pragma unroll
            for (int mf = 0; mf < 4; mf++)
                ldsm_x4(a[mf], AsB + (uint32_t)(wm * 64 + mf * 16) * ASTRIDE
                                     + aRowOff + ks * 32);
            uint32_t bb[8];
            ldsm_x4(&bb[0], BsB + bOff + ks * 32);
            ldsm_x4(&bb[4], BsB + 16 * ASTRIDE + bOff + ks * 32);
            #pragma unroll
            for (int nf = 0; nf < 4; nf++)
                #pragma unroll
                for (int mf = 0; mf < 4; mf++)
                    mma_bf16(c[mf][nf], a[mf], &bb[nf * 2]);
        }
    }

    uint8_t* Outb = which ? g_Qb : g_Pb;
    #pragma unroll
    for (int mf = 0; mf < 4; mf++) {
        #pragma unroll
        for (int nf = 0; nf < 4; nf++) {
            int r = m0 + wm * 64 + mf * 16 + g;
            int col = e0 + wn * 32 + nf * 8 + 2 * tg;   // even
            float b0 = 0.f, b1 = 0.f;
            if (!which) { b0 = bt[col]; b1 = bt[col + 1]; }
            // permuted store: block (col>>4)*32B, word slot 2tg + (nf&1)
            uint32_t pbyte = (uint32_t)(col >> 4) * 32 + (uint32_t)(2 * tg + (nf & 1)) * 4;
            *reinterpret_cast<uint32_t*>(Outb + (size_t)r * (DIMN * 2) + pbyte) =
                f2bf2(c[mf][nf][0] + b0, c[mf][nf][1] + b1);
            *reinterpret_cast<uint32_t*>(Outb + (size_t)(r + 8) * (DIMN * 2) + pbyte) =
                f2bf2(c[mf][nf][2] + b0, c[mf][nf][3] + b1);
        }
    }
}

// ---------------------------------------------------------------------------
// Kernel 2: fused pairwise scores + log-softmax, register-direct A fragments
// with permuted P/Q layout: one ld.shared.v2.b32 yields both k-halves of a
// fragment pair (was 2 scalar LDS). 9 LDS.64 per ks (1 q + 8 p), batched.
// Q stride 1056 -> rows on bank 8g, LDS.64 phases conflict-free.
// ---------------------------------------------------------------------------
#define QSTRIDE 1056
#define OFF_BPS 0
#define OFF_PB  1024                        // 16 x 1024 = 16384
#define OFF_QB  (OFF_PB + 16384)            // 8 x 1056 = 8448 -> ends 25856
#define OFF_B(s) (25856 + (s) * (128 * ASTRIDE))
#define REL_SMEM 68608                      // epilogue Ssm: 1024 + 128*132*4

__global__ __launch_bounds__(256, 2)
void rel_kernel(const float* __restrict__ bp,
                float* __restrict__ out)
{
    extern __shared__ __align__(16) char dsm[];
    const uint32_t smb = smem_u32(dsm);
    float* bps = reinterpret_cast<float*>(dsm + OFF_BPS);

    const int hblk = blockIdx.x;  // 0..11
    const int dblk = blockIdx.y;  // 0..5
    const int b = blockIdx.z;     // 0..15

    const int tid = threadIdx.x;
    const int wid = tid >> 5;
    const int lane = tid & 31;
    const int wm = wid >> 2;
    const int wn = wid & 3;
    const int g = lane >> 2;
    const int tg = lane & 3;

    if (tid < RELN) bps[tid] = bp[tid];

    float c[4][4][4];
    #pragma unroll
    for (int i = 0; i < 4; i++)
        #pragma unroll
        for (int j = 0; j < 4; j++)
            #pragma unroll
            for (int k = 0; k < 4; k++) c[i][j][k] = 0.f;

    // per-thread constant addresses (permuted layout: pair at tg*8)
    const uint32_t qb2 = smb + OFF_QB + (uint32_t)g * QSTRIDE + (uint32_t)tg * 8;
    const uint32_t pb2 = smb + OFF_PB + (uint32_t)(wm * 8) * 1024 + (uint32_t)tg * 8;

    const uint32_t bRow = (uint32_t)(wn * 32 + ((lane >> 4) << 3) + (lane & 7));
    const uint32_t bOff = bRow * ASTRIDE + (uint32_t)((lane >> 3) & 1) * 16;

    auto issue_B = [&](int j, int s) {
        const uint32_t stb = smb + OFF_B(s);
        #pragma unroll
        for (int i = 0; i < 4; i++) {
            int o = i * 256 + tid;
            int n = o >> 3, ch = o & 7;
            cp16(stb + (uint32_t)n * ASTRIDE + (uint32_t)ch * 16,
                 g_Wpb + (size_t)n * (DIMN * 2) + (size_t)j * 128 + (size_t)ch * 16);
        }
        CP_COMMIT();
    };

    // prologue: stage P (stride 1024), Q (stride 1056), B(0)
    {
        #pragma unroll
        for (int i = 0; i < 4; i++) {
            int o = i * 256 + tid;
            int row = o >> 6, ch = o & 63;
            cp16(smb + OFF_PB + (uint32_t)row * 1024 + (uint32_t)ch * 16,
                 g_Pb + ((size_t)(dblk * 16 + row) * BSZN + b) * 1024 + (size_t)ch * 16);
        }
        #pragma unroll
        for (int i = 0; i < 2; i++) {
            int o = i * 256 + tid;
            int row = o >> 6, ch = o & 63;
            cp16(smb + OFF_QB + (uint32_t)row * QSTRIDE + (uint32_t)ch * 16,
                 g_Qb + ((size_t)(hblk * 8 + row) * BSZN + b) * 1024 + (size_t)ch * 16);
        }
        CP_COMMIT();
        issue_B(0, 0);
        CP_WAIT0();
    }

    // mainloop: one sync per chunk
    #pragma unroll 1
    for (int j = 0; j < 8; j++) {
        const int cur = j & 1;
        __syncthreads();                // B(j) visible; stage cur^1 reads done
        if (j < 7) issue_B(j + 1, cur ^ 1);

        const uint32_t BsB = smb + OFF_B(cur);
        const uint32_t kchunk = (uint32_t)j * 128;
        uint32_t bb[2][8];
        ldsm_x4(&bb[0][0], BsB + bOff);
        ldsm_x4(&bb[0][4], BsB + 16 * ASTRIDE + bOff);
        #pragma unroll
        for (int ks = 0; ks < 4; ks++) {
            const int cu = ks & 1, nx = cu ^ 1;
            if (ks < 3) {
                ldsm_x4(&bb[nx][0], BsB + bOff + (ks + 1) * 32);
                ldsm_x4(&bb[nx][4], BsB + 16 * ASTRIDE + bOff + (ks + 1) * 32);
            }
            // batched operand loads: 1 q + 8 p LDS.64 (MLP=9)
            const uint32_t ko = kchunk + (uint32_t)ks * 32;
            uint2 q = lds64(qb2 + ko);
            uint2 p[4][2];
            #pragma unroll
            for (int mf = 0; mf < 4; mf++) {
                const uint32_t pb = pb2 + (uint32_t)mf * 2048 + ko;
                p[mf][0] = lds64(pb);
                p[mf][1] = lds64(pb + 1024);
            }
            #pragma unroll
            for (int mf = 0; mf < 4; mf++) {
                uint32_t a[4];
                a[0] = bf2_addrelu(p[mf][0].x, q.x);
                a[1] = bf2_addrelu(p[mf][1].x, q.x);
                a[2] = bf2_addrelu(p[mf][0].y, q.y);
                a[3] = bf2_addrelu(p[mf][1].y, q.y);
                #pragma unroll
                for (int nf = 0; nf < 4; nf++)
                    mma_bf16(c[mf][nf], a, &bb[cu][nf * 2]);
            }
        }

        if (j < 7) CP_WAIT0();
    }

    // single-pass epilogue: stage 128x132, per-row log-softmax
    float* Ssm = reinterpret_cast<float*>(dsm + 1024);
    __syncthreads();
    #pragma unroll
    for (int mf = 0; mf < 4; mf++) {
        #pragma unroll
        for (int nf = 0; nf < 4; nf++) {
            int rl = wm * 64 + mf * 16 + g;
            int col = wn * 32 + nf * 8 + 2 * tg;
            *reinterpret_cast<float2*>(&Ssm[rl * 132 + col]) =
                make_float2(c[mf][nf][0], c[mf][nf][1]);
            *reinterpret_cast<float2*>(&Ssm[(rl + 8) * 132 + col]) =
                make_float2(c[mf][nf][2], c[mf][nf][3]);
        }
    }
    __syncthreads();
    #pragma unroll
    for (int i = 0; i < 16; i++) {
        int rl = wid * 16 + i;
        float4 v = *reinterpret_cast<const float4*>(&Ssm[rl * 132 + lane * 4]);
        v.x += bps[lane * 4 + 0];
        v.y += bps[lane * 4 + 1];
        v.z += bps[lane * 4 + 2];
        v.w += bps[lane * 4 + 3];
        float mx = fmaxf(fmaxf(v.x, v.y), fmaxf(v.z, v.w));
        #pragma unroll
        for (int off = 16; off > 0; off >>= 1)
            mx = fmaxf(mx, __shfl_xor_sync(0xffffffffu, mx, off));
        mx = fmaxf(mx, 0.f);  // nil column
        float se = __expf(v.x - mx) + __expf(v.y - mx) +
                   __expf(v.z - mx) + __expf(v.w - mx);
        #pragma unroll
        for (int off = 16; off > 0; off >>= 1)
            se += __shfl_xor_sync(0xffffffffu, se, off);
        se += __expf(-mx);  // nil column contribution
        float lse = mx + __logf(se);
        int d = dblk * 16 + (rl >> 3);
        int h = hblk * 8 + (rl & 7);
        float* op = out + (size_t)((d * BSZN + b) * HEADN + h) * (RELN + 1);
        if (lane == 0) op[0] = -lse;
        op[1 + lane * 4 + 0] = v.x - lse;
        op[1 + lane * 4 + 1] = v.y - lse;
        op[1 + lane * 4 + 2] = v.z - lse;
        op[1 + lane * 4 + 3] = v.w - lse;
    }
}

// ---------------------------------------------------------------------------
extern "C" void kernel_launch(void* const* d_in, const int* in_sizes, int n_in,
                              void* d_out, int out_size) {
    const float* outs = (const float*)d_in[0];  // [96,16,512]
    const float* gs   = (const float*)d_in[1];  // [96,16,512]
    const float* Wt   = (const float*)d_in[2];  // [512,1024]
    const float* bt   = (const float*)d_in[3];  // [512]
    const float* Wp   = (const float*)d_in[4];  // [128,512]
    const float* bp   = (const float*)d_in[5];  // [128]
    float* out = (float*)d_out;                 // [96,16,96,129]

    (void)in_sizes; (void)n_in; (void)out_size;

    static bool attr_set = false;
    if (!attr_set) {
        cudaFuncSetAttribute(rel_kernel,
                             cudaFuncAttributeMaxDynamicSharedMemorySize,
                             REL_SMEM);
        cudaFuncSetAttribute(projb_kernel,
                             cudaFuncAttributeMaxDynamicSharedMemorySize,
                             PJ_SMEM);
        attr_set = true;
    }

    prep_kernel<<<R_WP / 256, 256>>>(outs, gs, Wt, Wp);        // 2112 blocks

    dim3 pg(DIMN / 128, 1536 / 128, 2);           // (4, 12, 2)
    projb_kernel<<<pg, 256, PJ_SMEM>>>(bt);

    dim3 mg(HEADN / 8, DEPN / 16, BSZN);          // (12, 6, 16)
    rel_kernel<<<mg, 256, REL_SMEM>>>(bp, out);
}